// round 5
// baseline (speedup 1.0000x reference)
#include <cuda_runtime.h>
#include <cstdint>

#define N_NODES 100000
#define N_EDGESC 1600000
#define N_GRAPHS 512
#define DH 128
#define DLAT 64
#define NCOND 7
#define BN_EPS 1e-5f

// ================= scratch (device globals; no allocation allowed) =================
__device__ float g_h2[N_NODES * DH];    // GEMM1 output
__device__ float g_x[N_NODES * DH];     // GEMM2 output (layer output)
__device__ uint4 g_Bpk[256 * 32];       // fragment-packed weights (hi/lo tf32)
__device__ float g_bias[DH];
__device__ int g_cnt[N_NODES];
__device__ int g_rowptr[N_NODES + 1];
__device__ int g_bsum[128];
__device__ int g_bscan[128];
__device__ int g_csr[N_EDGESC];
__device__ float g_sum[DH];
__device__ float g_sumsq[DH];
__device__ float g_a[DH];
__device__ float g_c[DH];
__device__ float g_pooled[N_GRAPHS * DH];
__device__ float g_pa[DH];
__device__ float g_pc[DH];
__device__ float g_h1[N_GRAPHS * DLAT];
__device__ float g_fa[DLAT];
__device__ float g_fc[DLAT];

// ================= helpers =================
__device__ __forceinline__ float leaky(float x) { return fmaxf(x, 0.2f * x); }
__device__ __forceinline__ void red_add_v4(float* p, float4 v) {
    asm volatile("red.global.add.v4.f32 [%0], {%1,%2,%3,%4};"
                 :: "l"(p), "f"(v.x), "f"(v.y), "f"(v.z), "f"(v.w) : "memory");
}
__device__ __forceinline__ void red_add_v2(float* p, float a, float b) {
    asm volatile("red.global.add.v2.f32 [%0], {%1,%2};"
                 :: "l"(p), "f"(a), "f"(b) : "memory");
}
__device__ __forceinline__ uint32_t f2tf32(float x) {
    uint32_t r;
    asm("cvt.rna.tf32.f32 %0, %1;" : "=r"(r) : "f"(x));
    return r;
}
__device__ __forceinline__ void mma_tf32(float* d, uint32_t a0, uint32_t a1,
                                         uint32_t a2, uint32_t a3,
                                         uint32_t b0, uint32_t b1) {
    asm volatile(
        "mma.sync.aligned.m16n8k8.row.col.f32.tf32.tf32.f32 "
        "{%0,%1,%2,%3}, {%4,%5,%6,%7}, {%8,%9}, {%0,%1,%2,%3};"
        : "+f"(d[0]), "+f"(d[1]), "+f"(d[2]), "+f"(d[3])
        : "r"(a0), "r"(a1), "r"(a2), "r"(a3), "r"(b0), "r"(b1));
}

// ================= zero =================
__global__ void zerok(float4* p, int n4) {
    int i = blockIdx.x * blockDim.x + threadIdx.x;
    if (i < n4) p[i] = make_float4(0.f, 0.f, 0.f, 0.f);
}

// ================= CSR build =================
__global__ void hist_k(const int* __restrict__ dst, int* __restrict__ cnt, int nE) {
    int i = blockIdx.x * blockDim.x + threadIdx.x;
    if (i < nE) atomicAdd(&cnt[dst[i]], 1);
}
__global__ void scan_block(const int* __restrict__ cnt, int* __restrict__ excl,
                           int* __restrict__ bsum, int n) {
    __shared__ int sm[1024];
    int i = blockIdx.x * 1024 + threadIdx.x;
    int v = (i < n) ? cnt[i] : 0;
    sm[threadIdx.x] = v;
    __syncthreads();
    for (int off = 1; off < 1024; off <<= 1) {
        int t = (threadIdx.x >= off) ? sm[threadIdx.x - off] : 0;
        __syncthreads();
        sm[threadIdx.x] += t;
        __syncthreads();
    }
    if (i < n) excl[i] = sm[threadIdx.x] - v;
    if (threadIdx.x == 1023) bsum[blockIdx.x] = sm[1023];
}
__global__ void scan_sums(const int* __restrict__ bsum, int* __restrict__ bscan, int nb) {
    __shared__ int sm[128];
    int t = threadIdx.x;
    int v = (t < nb) ? bsum[t] : 0;
    sm[t] = v;
    __syncthreads();
    for (int off = 1; off < 128; off <<= 1) {
        int u = (t >= off) ? sm[t - off] : 0;
        __syncthreads();
        sm[t] += u;
        __syncthreads();
    }
    if (t < nb) bscan[t] = sm[t] - v;
}
__global__ void add_off(int* __restrict__ rowptr, const int* __restrict__ bscan,
                        int* __restrict__ cursor, int n, int nE) {
    int i = blockIdx.x * blockDim.x + threadIdx.x;
    if (i < n) {
        int v = rowptr[i] + bscan[i >> 10];
        rowptr[i] = v;
        cursor[i] = v;
    }
    if (i == 0) rowptr[n] = nE;
}
__global__ void scatter_k(const int* __restrict__ src, const int* __restrict__ dst,
                          int* __restrict__ cursor, int* __restrict__ csr, int nE) {
    int i = blockIdx.x * blockDim.x + threadIdx.x;
    if (i < nE) {
        int pos = atomicAdd(&cursor[dst[i]], 1);
        csr[pos] = src[i];
    }
}

// ================= merged weight prep: packed tf32 hi/lo frags + folded bias =================
// Bpk layout: [kstep 16][tile 16][lane 32] uint4 = (hi(w@k), lo(w@k), hi(w@k+4), lo(w@k+4))
__global__ void __launch_bounds__(128) wprep2(
    const float* __restrict__ W, const float* __restrict__ bvec,
    const float* __restrict__ a, const float* __restrict__ c,
    uint4* __restrict__ Bpk, float* __restrict__ bout, int hasAff) {
    int n = blockIdx.x, k = threadIdx.x;
    float w = W[k * DH + n];
    float ws = hasAff ? a[k] * w : w;
    uint32_t hi = f2tf32(ws);
    uint32_t lo = f2tf32(ws - __uint_as_float(hi));
    int ks = k >> 3, t = n >> 3;
    int lane = ((n & 7) << 2) | (k & 3);
    int slot = (k >> 2) & 1;
    uint32_t* base = (uint32_t*)&Bpk[(ks * 16 + t) * 32 + lane];
    base[slot * 2] = hi;
    base[slot * 2 + 1] = lo;
    __shared__ float red[DH];
    red[k] = hasAff ? c[k] * w : 0.f;
    __syncthreads();
    for (int off = 64; off > 0; off >>= 1) {
        if (k < off) red[k] += red[k + off];
        __syncthreads();
    }
    if (k == 0) bout[n] = bvec[n] + red[0];
}

// ================= smem layout for GEMMs =================
#define AS_STRIDE 132
#define SM_B_OFF 67584                 // 128*132*4 = 67584
#define SM_BIAS_OFF 198656             // 67584 + 131072
#define GEMM_SMEM 199168

// ================= GEMM1 fused: gather + 3xTF32 GEMM + leaky + column stats =================
__global__ void __launch_bounds__(256, 1) gemm1_fused(
    const float4* __restrict__ x, const int* __restrict__ rowptr, const int* __restrict__ csr,
    const uint4* __restrict__ Bpk, const float* __restrict__ bias,
    float* __restrict__ out, float* __restrict__ gsum, float* __restrict__ gsq, int M) {
    extern __shared__ char smem[];
    float* As = (float*)smem;                 // 128 x 132 fp32
    uint4* Bs = (uint4*)(smem + SM_B_OFF);    // 256 x 32 uint4
    float* sb = (float*)(smem + SM_BIAS_OFF); // 128 fp32
    int tid = threadIdx.x;
    int warp = tid >> 5, lane = tid & 31;
    int row0 = blockIdx.x << 7;

    if (tid < 128) sb[tid] = bias[tid];
    // stage B (shared across warps)
#pragma unroll
    for (int it = 0; it < 32; it++) Bs[it * 256 + tid] = __ldg(Bpk + it * 256 + tid);

    // gather own 16 rows: As[r] = x[row] + sum_{nb} x[nb]
#pragma unroll 1
    for (int i = 0; i < 16; i++) {
        int r = warp * 16 + i;
        int grow = row0 + r;
        float4 acc = make_float4(0.f, 0.f, 0.f, 0.f);
        if (grow < M) {
            acc = __ldg(x + (size_t)grow * 32 + lane);
            int e0 = __ldg(rowptr + grow), e1 = __ldg(rowptr + grow + 1);
            int e = e0;
            for (; e + 4 <= e1; e += 4) {
                int s0 = __ldg(csr + e), s1 = __ldg(csr + e + 1);
                int s2 = __ldg(csr + e + 2), s3 = __ldg(csr + e + 3);
                float4 v0 = __ldg(x + (size_t)s0 * 32 + lane);
                float4 v1 = __ldg(x + (size_t)s1 * 32 + lane);
                float4 v2 = __ldg(x + (size_t)s2 * 32 + lane);
                float4 v3 = __ldg(x + (size_t)s3 * 32 + lane);
                acc.x += v0.x + v1.x + v2.x + v3.x;
                acc.y += v0.y + v1.y + v2.y + v3.y;
                acc.z += v0.z + v1.z + v2.z + v3.z;
                acc.w += v0.w + v1.w + v2.w + v3.w;
            }
            for (; e < e1; e++) {
                int s = __ldg(csr + e);
                float4 v = __ldg(x + (size_t)s * 32 + lane);
                acc.x += v.x; acc.y += v.y; acc.z += v.z; acc.w += v.w;
            }
        }
        *(float4*)(As + r * AS_STRIDE + lane * 4) = acc;
    }
    __syncthreads();

    int m0 = warp * 16;
    int gid = lane >> 2, qid = lane & 3;
    float acc[16][4];
#pragma unroll
    for (int t = 0; t < 16; t++)
#pragma unroll
        for (int j = 0; j < 4; j++) acc[t][j] = 0.f;

    const float* arow0 = As + (m0 + gid) * AS_STRIDE;
    const float* arow1 = As + (m0 + gid + 8) * AS_STRIDE;
#pragma unroll
    for (int ks = 0; ks < 16; ks++) {
        int kb = ks * 8 + qid;
        float a0 = arow0[kb], a1 = arow1[kb];
        float a2 = arow0[kb + 4], a3 = arow1[kb + 4];
        uint32_t ah0 = f2tf32(a0), ah1 = f2tf32(a1), ah2 = f2tf32(a2), ah3 = f2tf32(a3);
        uint32_t al0 = f2tf32(a0 - __uint_as_float(ah0));
        uint32_t al1 = f2tf32(a1 - __uint_as_float(ah1));
        uint32_t al2 = f2tf32(a2 - __uint_as_float(ah2));
        uint32_t al3 = f2tf32(a3 - __uint_as_float(ah3));
        const uint4* bp = Bs + ks * 512 + lane;
#pragma unroll
        for (int t = 0; t < 16; t++) {
            uint4 bv = bp[t * 32];
            mma_tf32(acc[t], ah0, ah1, ah2, ah3, bv.x, bv.z);
            mma_tf32(acc[t], ah0, ah1, ah2, ah3, bv.y, bv.w);
            mma_tf32(acc[t], al0, al1, al2, al3, bv.x, bv.z);
        }
    }

    // epilogue: bias + leaky, store, per-thread column partial stats
    int r0 = row0 + m0 + gid;
    int r1 = r0 + 8;
    float cs[32], cq[32];
#pragma unroll
    for (int t = 0; t < 16; t++) {
        int c = t * 8 + qid * 2;
        float b0 = sb[c], b1 = sb[c + 1];
        float v00 = 0.f, v01 = 0.f, v10 = 0.f, v11 = 0.f;
        if (r0 < M) {
            v00 = leaky(acc[t][0] + b0);
            v01 = leaky(acc[t][1] + b1);
            *(float2*)(out + (size_t)r0 * DH + c) = make_float2(v00, v01);
        }
        if (r1 < M) {
            v10 = leaky(acc[t][2] + b0);
            v11 = leaky(acc[t][3] + b1);
            *(float2*)(out + (size_t)r1 * DH + c) = make_float2(v10, v11);
        }
        cs[2 * t] = v00 + v10;
        cs[2 * t + 1] = v01 + v11;
        cq[2 * t] = v00 * v00 + v10 * v10;
        cq[2 * t + 1] = v01 * v01 + v11 * v11;
    }

    __syncthreads();  // mainloop reads of As done everywhere; reuse As as stats scratch
    float* ssum = As;          // [64][128]
    float* ssq = As + 8192;    // [64][128]
    int slot = warp * 8 + gid; // 0..63
#pragma unroll
    for (int t = 0; t < 16; t++) {
        int c = t * 8 + qid * 2;
        ssum[slot * 128 + c] = cs[2 * t];
        ssum[slot * 128 + c + 1] = cs[2 * t + 1];
        ssq[slot * 128 + c] = cq[2 * t];
        ssq[slot * 128 + c + 1] = cq[2 * t + 1];
    }
    __syncthreads();
    if (tid < 128) {
        float s = 0.f;
#pragma unroll
        for (int w = 0; w < 64; w++) s += ssum[w * 128 + tid];
        atomicAdd(&gsum[tid], s);
    } else {
        int c = tid - 128;
        float q = 0.f;
#pragma unroll
        for (int w = 0; w < 64; w++) q += ssq[w * 128 + c];
        atomicAdd(&gsq[c], q);
    }
}

// ================= GEMM2: 3xTF32 GEMM + leaky; mode0: store out; mode1: pool-only =================
__global__ void __launch_bounds__(256, 1) gemm_tc(
    const float4* __restrict__ A, const uint4* __restrict__ Bpk,
    const float* __restrict__ bias, float* __restrict__ out,
    const int* __restrict__ batch, float* __restrict__ pooled,
    int M, int doPool) {
    extern __shared__ char smem[];
    float* As = (float*)smem;
    uint4* Bs = (uint4*)(smem + SM_B_OFF);
    float* sb = (float*)(smem + SM_BIAS_OFF);
    int tid = threadIdx.x;
    int row0 = blockIdx.x << 7;

    if (tid < 128) sb[tid] = bias[tid];
#pragma unroll
    for (int it = 0; it < 16; it++) {
        int idx = it * 256 + tid;
        int r = idx >> 5, c4 = idx & 31;
        int gr = row0 + r;
        float4 v = make_float4(0.f, 0.f, 0.f, 0.f);
        if (gr < M) v = __ldg(A + (size_t)gr * 32 + c4);
        *(float4*)(As + r * AS_STRIDE + c4 * 4) = v;
    }
#pragma unroll
    for (int it = 0; it < 32; it++) Bs[it * 256 + tid] = __ldg(Bpk + it * 256 + tid);
    __syncthreads();

    int warp = tid >> 5, lane = tid & 31;
    int m0 = warp * 16;
    int gid = lane >> 2, qid = lane & 3;
    float acc[16][4];
#pragma unroll
    for (int t = 0; t < 16; t++)
#pragma unroll
        for (int j = 0; j < 4; j++) acc[t][j] = 0.f;

    const float* arow0 = As + (m0 + gid) * AS_STRIDE;
    const float* arow1 = As + (m0 + gid + 8) * AS_STRIDE;
#pragma unroll
    for (int ks = 0; ks < 16; ks++) {
        int kb = ks * 8 + qid;
        float a0 = arow0[kb], a1 = arow1[kb];
        float a2 = arow0[kb + 4], a3 = arow1[kb + 4];
        uint32_t ah0 = f2tf32(a0), ah1 = f2tf32(a1), ah2 = f2tf32(a2), ah3 = f2tf32(a3);
        uint32_t al0 = f2tf32(a0 - __uint_as_float(ah0));
        uint32_t al1 = f2tf32(a1 - __uint_as_float(ah1));
        uint32_t al2 = f2tf32(a2 - __uint_as_float(ah2));
        uint32_t al3 = f2tf32(a3 - __uint_as_float(ah3));
        const uint4* bp = Bs + ks * 512 + lane;
#pragma unroll
        for (int t = 0; t < 16; t++) {
            uint4 bv = bp[t * 32];
            mma_tf32(acc[t], ah0, ah1, ah2, ah3, bv.x, bv.z);
            mma_tf32(acc[t], ah0, ah1, ah2, ah3, bv.y, bv.w);
            mma_tf32(acc[t], al0, al1, al2, al3, bv.x, bv.z);
        }
    }

    int r0 = row0 + m0 + gid;
    int r1 = r0 + 8;
    if (!doPool) {
#pragma unroll
        for (int t = 0; t < 16; t++) {
            int c = t * 8 + qid * 2;
            float b0 = sb[c], b1 = sb[c + 1];
            if (r0 < M)
                *(float2*)(out + (size_t)r0 * DH + c) =
                    make_float2(leaky(acc[t][0] + b0), leaky(acc[t][1] + b1));
            if (r1 < M)
                *(float2*)(out + (size_t)r1 * DH + c) =
                    make_float2(leaky(acc[t][2] + b0), leaky(acc[t][3] + b1));
        }
    } else {
        int b0g = (r0 < M) ? __ldg(batch + r0) : 0;
        int b1g = (r1 < M) ? __ldg(batch + r1) : 0;
#pragma unroll
        for (int t = 0; t < 16; t++) {
            int c = t * 8 + qid * 2;
            float b0 = sb[c], b1 = sb[c + 1];
            if (r0 < M)
                red_add_v2(pooled + (size_t)b0g * DH + c,
                           leaky(acc[t][0] + b0), leaky(acc[t][1] + b1));
            if (r1 < M)
                red_add_v2(pooled + (size_t)b1g * DH + c,
                           leaky(acc[t][2] + b0), leaky(acc[t][3] + b1));
        }
    }
}

// ================= sums -> folded BN affine (also zeroes accumulators) =================
__global__ void bn_prep(float* __restrict__ sum, float* __restrict__ sumsq,
                        float n, const float* __restrict__ g, const float* __restrict__ b,
                        float* __restrict__ oa, float* __restrict__ oc, int D) {
    int c = threadIdx.x;
    if (c < D) {
        float m = sum[c] / n;
        float v = sumsq[c] / n - m * m;
        float r = rsqrtf(v + BN_EPS);
        oa[c] = g[c] * r;
        oc[c] = b[c] - g[c] * m * r;
        sum[c] = 0.f;
        sumsq[c] = 0.f;
    }
}

// ================= small column stats (pooled / h1) =================
__global__ void colstats(const float* __restrict__ data, int rows, int cols,
                         const float* __restrict__ g, const float* __restrict__ b,
                         float* __restrict__ oa, float* __restrict__ oc) {
    int col = blockIdx.x;
    int t = threadIdx.x;
    float s = 0.f, q = 0.f;
    for (int r = t; r < rows; r += blockDim.x) {
        float v = data[(size_t)r * cols + col];
        s += v; q += v * v;
    }
    __shared__ float ss[256], qq[256];
    ss[t] = s; qq[t] = q;
    __syncthreads();
    for (int off = 128; off > 0; off >>= 1) {
        if (t < off) { ss[t] += ss[t + off]; qq[t] += qq[t + off]; }
        __syncthreads();
    }
    if (t == 0) {
        float m = ss[0] / rows;
        float v = qq[0] / rows - m * m;
        float r = rsqrtf(v + BN_EPS);
        oa[col] = g[col] * r;
        oc[col] = b[col] - g[col] * m * r;
    }
}

// ================= head =================
__global__ void __launch_bounds__(64) head1(
    const float* __restrict__ pooled, const float* __restrict__ pa, const float* __restrict__ pc,
    const float* __restrict__ fcW, const float* __restrict__ fcb,
    const float* __restrict__ feats,
    const float* __restrict__ cW1, const float* __restrict__ cb1,
    const float* __restrict__ cW2, const float* __restrict__ cb2,
    const float* __restrict__ fW1, const float* __restrict__ fb1,
    float* __restrict__ h1out) {
    int g = blockIdx.x;
    int j = threadIdx.x;
    __shared__ float cat[DLAT + 8];
    float o = fcb[j];
    const float* pr = pooled + (size_t)g * DH;
    for (int k = 0; k < DH; k++) o += (pr[k] * pa[k] + pc[k]) * fcW[k * DLAT + j];
    cat[j] = o;
    if (j < 8) {
        float c1[8];
#pragma unroll
        for (int i = 0; i < 8; i++) {
            float a = cb1[i];
#pragma unroll
            for (int m = 0; m < NCOND; m++) a += feats[g * NCOND + m] * cW1[m * 8 + i];
            c1[i] = fmaxf(a, 0.f);
        }
        float o2 = cb2[j];
#pragma unroll
        for (int i = 0; i < 8; i++) o2 += c1[i] * cW2[i * 8 + j];
        cat[DLAT + j] = o2;
    }
    __syncthreads();
    float h = fb1[j];
    for (int k = 0; k < DLAT + 8; k++) h += cat[k] * fW1[k * DLAT + j];
    h1out[(size_t)g * DLAT + j] = leaky(h);
}

__global__ void __launch_bounds__(64) head2(
    const float* __restrict__ h1, const float* __restrict__ fa, const float* __restrict__ fc,
    const float* __restrict__ fW2, const float* __restrict__ fb2,
    float* __restrict__ out) {
    int g = blockIdx.x;
    int j = threadIdx.x;
    __shared__ float hn[DLAT];
    hn[j] = h1[(size_t)g * DLAT + j] * fa[j] + fc[j];
    __syncthreads();
    float o = fb2[j];
    for (int k = 0; k < DLAT; k++) o += hn[k] * fW2[k * DLAT + j];
    out[(size_t)g * DLAT + j] = o;
}

// ================= launch =================
extern "C" void kernel_launch(void* const* d_in, const int* in_sizes, int n_in,
                              void* d_out, int out_size) {
    const float* x      = (const float*)d_in[0];
    const int*   ei     = (const int*)d_in[1];
    const int*   batch  = (const int*)d_in[2];
    const float* feats  = (const float*)d_in[3];
    const float* convW1 = (const float*)d_in[4];
    const float* convb1 = (const float*)d_in[5];
    const float* convg1 = (const float*)d_in[6];
    const float* convbb1= (const float*)d_in[7];
    const float* convW2 = (const float*)d_in[8];
    const float* convb2 = (const float*)d_in[9];
    const float* bng    = (const float*)d_in[10];
    const float* bnb    = (const float*)d_in[11];
    const float* fcW    = (const float*)d_in[12];
    const float* fcb    = (const float*)d_in[13];
    const float* cW1    = (const float*)d_in[14];
    const float* cb1    = (const float*)d_in[15];
    const float* cW2    = (const float*)d_in[16];
    const float* cb2    = (const float*)d_in[17];
    const float* fW1    = (const float*)d_in[18];
    const float* fb1    = (const float*)d_in[19];
    const float* fg     = (const float*)d_in[20];
    const float* fb_    = (const float*)d_in[21];
    const float* fW2    = (const float*)d_in[22];
    const float* fb2    = (const float*)d_in[23];
    float* dout = (float*)d_out;

    int nE = in_sizes[1] / 2;
    const int* src = ei;
    const int* dst = ei + nE;
    int M = in_sizes[0] / DH;
    int G = in_sizes[3] / NCOND;

    float *p_h2, *p_x, *p_bias, *p_sum, *p_sq, *p_a, *p_c;
    float *p_pool, *p_pa, *p_pc, *p_h1, *p_fa, *p_fc;
    uint4* p_Bpk;
    int *p_cnt, *p_rowptr, *p_bsum, *p_bscan, *p_csr;
    cudaGetSymbolAddress((void**)&p_h2, g_h2);
    cudaGetSymbolAddress((void**)&p_x, g_x);
    cudaGetSymbolAddress((void**)&p_Bpk, g_Bpk);
    cudaGetSymbolAddress((void**)&p_bias, g_bias);
    cudaGetSymbolAddress((void**)&p_cnt, g_cnt);
    cudaGetSymbolAddress((void**)&p_rowptr, g_rowptr);
    cudaGetSymbolAddress((void**)&p_bsum, g_bsum);
    cudaGetSymbolAddress((void**)&p_bscan, g_bscan);
    cudaGetSymbolAddress((void**)&p_csr, g_csr);
    cudaGetSymbolAddress((void**)&p_sum, g_sum);
    cudaGetSymbolAddress((void**)&p_sq, g_sumsq);
    cudaGetSymbolAddress((void**)&p_a, g_a);
    cudaGetSymbolAddress((void**)&p_c, g_c);
    cudaGetSymbolAddress((void**)&p_pool, g_pooled);
    cudaGetSymbolAddress((void**)&p_pa, g_pa);
    cudaGetSymbolAddress((void**)&p_pc, g_pc);
    cudaGetSymbolAddress((void**)&p_h1, g_h1);
    cudaGetSymbolAddress((void**)&p_fa, g_fa);
    cudaGetSymbolAddress((void**)&p_fc, g_fc);

    cudaFuncSetAttribute(gemm1_fused, cudaFuncAttributeMaxDynamicSharedMemorySize, GEMM_SMEM);
    cudaFuncSetAttribute(gemm_tc, cudaFuncAttributeMaxDynamicSharedMemorySize, GEMM_SMEM);

    // ---- CSR build ----
    zerok<<<(N_NODES / 4 + 255) / 256, 256>>>((float4*)p_cnt, N_NODES / 4);
    hist_k<<<(nE + 255) / 256, 256>>>(dst, p_cnt, nE);
    int nb = (M + 1023) / 1024;
    scan_block<<<nb, 1024>>>(p_cnt, p_rowptr, p_bsum, M);
    scan_sums<<<1, 128>>>(p_bsum, p_bscan, nb);
    add_off<<<(M + 255) / 256, 256>>>(p_rowptr, p_bscan, p_cnt, M, nE);
    scatter_k<<<(nE + 255) / 256, 256>>>(src, dst, p_cnt, p_csr, nE);

    // ---- zero stats + pooled once ----
    zerok<<<1, 64>>>((float4*)p_sum, DH / 4);
    zerok<<<1, 64>>>((float4*)p_sq, DH / 4);
    zerok<<<(N_GRAPHS * DH / 4 + 255) / 256, 256>>>((float4*)p_pool, N_GRAPHS * DH / 4);

    int gemmGrid = (M + 127) / 128;
    const float* xcur = x;
    for (int l = 0; l < 3; l++) {
        wprep2<<<DH, DH>>>(convW1 + (size_t)l * DH * DH, convb1 + l * DH,
                           nullptr, nullptr, p_Bpk, p_bias, 0);
        gemm1_fused<<<gemmGrid, 256, GEMM_SMEM>>>(
            (const float4*)xcur, p_rowptr, p_csr, p_Bpk, p_bias, p_h2, p_sum, p_sq, M);
        bn_prep<<<1, DH>>>(p_sum, p_sq, (float)M, convg1 + l * DH, convbb1 + l * DH, p_a, p_c, DH);
        wprep2<<<DH, DH>>>(convW2 + (size_t)l * DH * DH, convb2 + l * DH,
                           p_a, p_c, p_Bpk, p_bias, 1);
        gemm_tc<<<gemmGrid, 256, GEMM_SMEM>>>(
            (const float4*)p_h2, p_Bpk, p_bias, p_x, batch, p_pool, M, (l == 2) ? 1 : 0);
        xcur = p_x;
    }

    colstats<<<DH, 256>>>(p_pool, G, DH, bng, bnb, p_pa, p_pc);
    head1<<<G, 64>>>(p_pool, p_pa, p_pc, fcW, fcb, feats, cW1, cb1, cW2, cb2, fW1, fb1, p_h1);
    colstats<<<DLAT, 256>>>(p_h1, G, DLAT, fg, fb_, p_fa, p_fc);
    head2<<<G, 64>>>(p_h1, p_fa, p_fc, fW2, fb2, dout);
}

// round 6
// speedup vs baseline: 1.3631x; 1.3631x over previous
#include <cuda_runtime.h>
#include <cstdint>

#define N_NODES 100000
#define N_EDGESC 1600000
#define N_GRAPHS 512
#define DH 128
#define DLAT 64
#define NCOND 7
#define BN_EPS 1e-5f

// ================= scratch (device globals; no allocation allowed) =================
__device__ float g_h[N_NODES * DH];     // gathered h (GEMM1 input)
__device__ float g_h2[N_NODES * DH];    // GEMM1 output
__device__ float g_x[N_NODES * DH];     // GEMM2 output (layer output)
__device__ uint4 g_Bpk[256 * 32];       // fragment-packed weights (hi/lo tf32)
__device__ float g_bias[DH];
__device__ int g_cnt[N_NODES];
__device__ int g_rowptr[N_NODES + 1];
__device__ int g_bsum[128];
__device__ int g_bscan[128];
__device__ int g_csr[N_EDGESC];
__device__ float g_sum[DH];
__device__ float g_sumsq[DH];
__device__ float g_a[DH];
__device__ float g_c[DH];
__device__ float g_pooled[N_GRAPHS * DH];
__device__ float g_pa[DH];
__device__ float g_pc[DH];
__device__ float g_h1[N_GRAPHS * DLAT];
__device__ float g_fa[DLAT];
__device__ float g_fc[DLAT];

// ================= helpers =================
__device__ __forceinline__ float leaky(float x) { return fmaxf(x, 0.2f * x); }
__device__ __forceinline__ void red_add_v2(float* p, float a, float b) {
    asm volatile("red.global.add.v2.f32 [%0], {%1,%2};"
                 :: "l"(p), "f"(a), "f"(b) : "memory");
}
__device__ __forceinline__ uint32_t f2tf32(float x) {
    uint32_t r;
    asm("cvt.rna.tf32.f32 %0, %1;" : "=r"(r) : "f"(x));
    return r;
}
__device__ __forceinline__ void mma_tf32(float* d, uint32_t a0, uint32_t a1,
                                         uint32_t a2, uint32_t a3,
                                         uint32_t b0, uint32_t b1) {
    asm volatile(
        "mma.sync.aligned.m16n8k8.row.col.f32.tf32.tf32.f32 "
        "{%0,%1,%2,%3}, {%4,%5,%6,%7}, {%8,%9}, {%0,%1,%2,%3};"
        : "+f"(d[0]), "+f"(d[1]), "+f"(d[2]), "+f"(d[3])
        : "r"(a0), "r"(a1), "r"(a2), "r"(a3), "r"(b0), "r"(b1));
}

// ================= zero =================
__global__ void zerok(float4* p, int n4) {
    int i = blockIdx.x * blockDim.x + threadIdx.x;
    if (i < n4) p[i] = make_float4(0.f, 0.f, 0.f, 0.f);
}

// ================= CSR build =================
__global__ void hist_k(const int* __restrict__ dst, int* __restrict__ cnt, int nE) {
    int i = blockIdx.x * blockDim.x + threadIdx.x;
    if (i < nE) atomicAdd(&cnt[dst[i]], 1);
}
__global__ void scan_block(const int* __restrict__ cnt, int* __restrict__ excl,
                           int* __restrict__ bsum, int n) {
    __shared__ int sm[1024];
    int i = blockIdx.x * 1024 + threadIdx.x;
    int v = (i < n) ? cnt[i] : 0;
    sm[threadIdx.x] = v;
    __syncthreads();
    for (int off = 1; off < 1024; off <<= 1) {
        int t = (threadIdx.x >= off) ? sm[threadIdx.x - off] : 0;
        __syncthreads();
        sm[threadIdx.x] += t;
        __syncthreads();
    }
    if (i < n) excl[i] = sm[threadIdx.x] - v;
    if (threadIdx.x == 1023) bsum[blockIdx.x] = sm[1023];
}
__global__ void scan_sums(const int* __restrict__ bsum, int* __restrict__ bscan, int nb) {
    __shared__ int sm[128];
    int t = threadIdx.x;
    int v = (t < nb) ? bsum[t] : 0;
    sm[t] = v;
    __syncthreads();
    for (int off = 1; off < 128; off <<= 1) {
        int u = (t >= off) ? sm[t - off] : 0;
        __syncthreads();
        sm[t] += u;
        __syncthreads();
    }
    if (t < nb) bscan[t] = sm[t] - v;
}
__global__ void add_off(int* __restrict__ rowptr, const int* __restrict__ bscan,
                        int* __restrict__ cursor, int n, int nE) {
    int i = blockIdx.x * blockDim.x + threadIdx.x;
    if (i < n) {
        int v = rowptr[i] + bscan[i >> 10];
        rowptr[i] = v;
        cursor[i] = v;
    }
    if (i == 0) rowptr[n] = nE;
}
__global__ void scatter_k(const int* __restrict__ src, const int* __restrict__ dst,
                          int* __restrict__ cursor, int* __restrict__ csr, int nE) {
    int i = blockIdx.x * blockDim.x + threadIdx.x;
    if (i < nE) {
        int pos = atomicAdd(&cursor[dst[i]], 1);
        csr[pos] = src[i];
    }
}

// ================= gather: h = x[node] + sum_{nb in CSR} x[nb] =================
__global__ void __launch_bounds__(256) gather_f32(
    const float* __restrict__ x, const int* __restrict__ rowptr, const int* __restrict__ csr,
    float* __restrict__ h, int M) {
    int node = blockIdx.x * 8 + (threadIdx.x >> 5);
    if (node >= M) return;
    int lane = threadIdx.x & 31;
    const float4* xv = (const float4*)x;
    float4 acc = __ldg(xv + (size_t)node * 32 + lane);
    int e0 = __ldg(rowptr + node), e1 = __ldg(rowptr + node + 1);
    int e = e0;
    for (; e + 4 <= e1; e += 4) {
        int s0 = __ldg(csr + e), s1 = __ldg(csr + e + 1);
        int s2 = __ldg(csr + e + 2), s3 = __ldg(csr + e + 3);
        float4 v0 = __ldg(xv + (size_t)s0 * 32 + lane);
        float4 v1 = __ldg(xv + (size_t)s1 * 32 + lane);
        float4 v2 = __ldg(xv + (size_t)s2 * 32 + lane);
        float4 v3 = __ldg(xv + (size_t)s3 * 32 + lane);
        acc.x += v0.x + v1.x + v2.x + v3.x;
        acc.y += v0.y + v1.y + v2.y + v3.y;
        acc.z += v0.z + v1.z + v2.z + v3.z;
        acc.w += v0.w + v1.w + v2.w + v3.w;
    }
    for (; e < e1; e++) {
        int s = __ldg(csr + e);
        float4 v = __ldg(xv + (size_t)s * 32 + lane);
        acc.x += v.x; acc.y += v.y; acc.z += v.z; acc.w += v.w;
    }
    ((float4*)(h + (size_t)node * DH))[lane] = acc;
}

// ================= merged weight prep: packed tf32 hi/lo frags + folded bias =================
// Bpk layout: [kstep 16][tile 16][lane 32] uint4 = (hi(w@k), lo(w@k), hi(w@k+4), lo(w@k+4))
__global__ void __launch_bounds__(128) wprep2(
    const float* __restrict__ W, const float* __restrict__ bvec,
    const float* __restrict__ a, const float* __restrict__ c,
    uint4* __restrict__ Bpk, float* __restrict__ bout, int hasAff) {
    int n = blockIdx.x, k = threadIdx.x;
    float w = W[k * DH + n];
    float ws = hasAff ? a[k] * w : w;
    uint32_t hi = f2tf32(ws);
    uint32_t lo = f2tf32(ws - __uint_as_float(hi));
    int ks = k >> 3, t = n >> 3;
    int lane = ((n & 7) << 2) | (k & 3);
    int slot = (k >> 2) & 1;
    uint32_t* base = (uint32_t*)&Bpk[(ks * 16 + t) * 32 + lane];
    base[slot * 2] = hi;
    base[slot * 2 + 1] = lo;
    __shared__ float red[DH];
    red[k] = hasAff ? c[k] * w : 0.f;
    __syncthreads();
    for (int off = 64; off > 0; off >>= 1) {
        if (k < off) red[k] += red[k + off];
        __syncthreads();
    }
    if (k == 0) bout[n] = bvec[n] + red[0];
}

// ================= smem layout for GEMMs =================
#define AS_STRIDE 132
#define SM_B_OFF 67584                 // 128*132*4
#define SM_BIAS_OFF 198656             // 67584 + 131072
#define GEMM_SMEM 199168

// ================= GEMM mainloop (shared) =================
__device__ __forceinline__ void gemm_mainloop(
    const float4* __restrict__ A, const uint4* __restrict__ Bpk,
    const float* __restrict__ bias, float* As, uint4* Bs, float* sb,
    int tid, int row0, int M, float acc[16][4]) {
    if (tid < 128) sb[tid] = bias[tid];
#pragma unroll
    for (int it = 0; it < 16; it++) {
        int idx = it * 256 + tid;
        int r = idx >> 5, c4 = idx & 31;
        int gr = row0 + r;
        float4 v = make_float4(0.f, 0.f, 0.f, 0.f);
        if (gr < M) v = __ldg(A + (size_t)gr * 32 + c4);
        *(float4*)(As + r * AS_STRIDE + c4 * 4) = v;
    }
#pragma unroll
    for (int it = 0; it < 32; it++) Bs[it * 256 + tid] = __ldg(Bpk + it * 256 + tid);
    __syncthreads();

    int warp = tid >> 5, lane = tid & 31;
    int m0 = warp * 16;
    int gid = lane >> 2, qid = lane & 3;
#pragma unroll
    for (int t = 0; t < 16; t++)
#pragma unroll
        for (int j = 0; j < 4; j++) acc[t][j] = 0.f;

    const float* arow0 = As + (m0 + gid) * AS_STRIDE;
    const float* arow1 = As + (m0 + gid + 8) * AS_STRIDE;
#pragma unroll
    for (int ks = 0; ks < 16; ks++) {
        int kb = ks * 8 + qid;
        float a0 = arow0[kb], a1 = arow1[kb];
        float a2 = arow0[kb + 4], a3 = arow1[kb + 4];
        uint32_t ah0 = f2tf32(a0), ah1 = f2tf32(a1), ah2 = f2tf32(a2), ah3 = f2tf32(a3);
        uint32_t al0 = f2tf32(a0 - __uint_as_float(ah0));
        uint32_t al1 = f2tf32(a1 - __uint_as_float(ah1));
        uint32_t al2 = f2tf32(a2 - __uint_as_float(ah2));
        uint32_t al3 = f2tf32(a3 - __uint_as_float(ah3));
        const uint4* bp = Bs + ks * 512 + lane;
#pragma unroll
        for (int t = 0; t < 16; t++) {
            uint4 bv = bp[t * 32];
            mma_tf32(acc[t], ah0, ah1, ah2, ah3, bv.x, bv.z);
            mma_tf32(acc[t], ah0, ah1, ah2, ah3, bv.y, bv.w);
            mma_tf32(acc[t], al0, al1, al2, al3, bv.x, bv.z);
        }
    }
}

// ================= GEMM1: 3xTF32 + leaky + fused column stats =================
__global__ void __launch_bounds__(256, 1) gemm1_stats(
    const float4* __restrict__ A, const uint4* __restrict__ Bpk,
    const float* __restrict__ bias, float* __restrict__ out,
    float* __restrict__ gsum, float* __restrict__ gsq, int M) {
    extern __shared__ char smem[];
    float* As = (float*)smem;
    uint4* Bs = (uint4*)(smem + SM_B_OFF);
    float* sb = (float*)(smem + SM_BIAS_OFF);
    int tid = threadIdx.x;
    int warp = tid >> 5, lane = tid & 31;
    int row0 = blockIdx.x << 7;
    float acc[16][4];
    gemm_mainloop(A, Bpk, bias, As, Bs, sb, tid, row0, M, acc);

    int gid = lane >> 2, qid = lane & 3;
    int r0 = row0 + warp * 16 + gid;
    int r1 = r0 + 8;
    float cs[32], cq[32];
#pragma unroll
    for (int t = 0; t < 16; t++) {
        int c = t * 8 + qid * 2;
        float b0 = sb[c], b1 = sb[c + 1];
        float v00 = 0.f, v01 = 0.f, v10 = 0.f, v11 = 0.f;
        if (r0 < M) {
            v00 = leaky(acc[t][0] + b0);
            v01 = leaky(acc[t][1] + b1);
            *(float2*)(out + (size_t)r0 * DH + c) = make_float2(v00, v01);
        }
        if (r1 < M) {
            v10 = leaky(acc[t][2] + b0);
            v11 = leaky(acc[t][3] + b1);
            *(float2*)(out + (size_t)r1 * DH + c) = make_float2(v10, v11);
        }
        cs[2 * t] = v00 + v10;
        cs[2 * t + 1] = v01 + v11;
        cq[2 * t] = v00 * v00 + v10 * v10;
        cq[2 * t + 1] = v01 * v01 + v11 * v11;
    }

    __syncthreads();  // all mainloop As reads done; reuse As as stats scratch
    float* ssum = As;          // [64][128]
    float* ssq = As + 8192;    // [64][128]
    int slot = warp * 8 + gid;
#pragma unroll
    for (int t = 0; t < 16; t++) {
        int c = t * 8 + qid * 2;
        ssum[slot * 128 + c] = cs[2 * t];
        ssum[slot * 128 + c + 1] = cs[2 * t + 1];
        ssq[slot * 128 + c] = cq[2 * t];
        ssq[slot * 128 + c + 1] = cq[2 * t + 1];
    }
    __syncthreads();
    if (tid < 128) {
        float s = 0.f;
#pragma unroll
        for (int w = 0; w < 64; w++) s += ssum[w * 128 + tid];
        atomicAdd(&gsum[tid], s);
    } else {
        int c = tid - 128;
        float q = 0.f;
#pragma unroll
        for (int w = 0; w < 64; w++) q += ssq[w * 128 + c];
        atomicAdd(&gsq[c], q);
    }
}

// ================= GEMM2: 3xTF32 + leaky; mode0: store; mode1: pool-only =================
__global__ void __launch_bounds__(256, 1) gemm2_pool(
    const float4* __restrict__ A, const uint4* __restrict__ Bpk,
    const float* __restrict__ bias, float* __restrict__ out,
    const int* __restrict__ batch, float* __restrict__ pooled,
    int M, int doPool) {
    extern __shared__ char smem[];
    float* As = (float*)smem;
    uint4* Bs = (uint4*)(smem + SM_B_OFF);
    float* sb = (float*)(smem + SM_BIAS_OFF);
    int tid = threadIdx.x;
    int warp = tid >> 5, lane = tid & 31;
    int row0 = blockIdx.x << 7;
    float acc[16][4];
    gemm_mainloop(A, Bpk, bias, As, Bs, sb, tid, row0, M, acc);

    int gid = lane >> 2, qid = lane & 3;
    int r0 = row0 + warp * 16 + gid;
    int r1 = r0 + 8;
    if (!doPool) {
#pragma unroll
        for (int t = 0; t < 16; t++) {
            int c = t * 8 + qid * 2;
            float b0 = sb[c], b1 = sb[c + 1];
            if (r0 < M)
                *(float2*)(out + (size_t)r0 * DH + c) =
                    make_float2(leaky(acc[t][0] + b0), leaky(acc[t][1] + b1));
            if (r1 < M)
                *(float2*)(out + (size_t)r1 * DH + c) =
                    make_float2(leaky(acc[t][2] + b0), leaky(acc[t][3] + b1));
        }
    } else {
        int b0g = (r0 < M) ? __ldg(batch + r0) : 0;
        int b1g = (r1 < M) ? __ldg(batch + r1) : 0;
#pragma unroll
        for (int t = 0; t < 16; t++) {
            int c = t * 8 + qid * 2;
            float b0 = sb[c], b1 = sb[c + 1];
            if (r0 < M)
                red_add_v2(pooled + (size_t)b0g * DH + c,
                           leaky(acc[t][0] + b0), leaky(acc[t][1] + b1));
            if (r1 < M)
                red_add_v2(pooled + (size_t)b1g * DH + c,
                           leaky(acc[t][2] + b0), leaky(acc[t][3] + b1));
        }
    }
}

// ================= sums -> folded BN affine (also zeroes accumulators) =================
__global__ void bn_prep(float* __restrict__ sum, float* __restrict__ sumsq,
                        float n, const float* __restrict__ g, const float* __restrict__ b,
                        float* __restrict__ oa, float* __restrict__ oc, int D) {
    int c = threadIdx.x;
    if (c < D) {
        float m = sum[c] / n;
        float v = sumsq[c] / n - m * m;
        float r = rsqrtf(v + BN_EPS);
        oa[c] = g[c] * r;
        oc[c] = b[c] - g[c] * m * r;
        sum[c] = 0.f;
        sumsq[c] = 0.f;
    }
}

// ================= small column stats (pooled / h1) =================
__global__ void colstats(const float* __restrict__ data, int rows, int cols,
                         const float* __restrict__ g, const float* __restrict__ b,
                         float* __restrict__ oa, float* __restrict__ oc) {
    int col = blockIdx.x;
    int t = threadIdx.x;
    float s = 0.f, q = 0.f;
    for (int r = t; r < rows; r += blockDim.x) {
        float v = data[(size_t)r * cols + col];
        s += v; q += v * v;
    }
    __shared__ float ss[256], qq[256];
    ss[t] = s; qq[t] = q;
    __syncthreads();
    for (int off = 128; off > 0; off >>= 1) {
        if (t < off) { ss[t] += ss[t + off]; qq[t] += qq[t + off]; }
        __syncthreads();
    }
    if (t == 0) {
        float m = ss[0] / rows;
        float v = qq[0] / rows - m * m;
        float r = rsqrtf(v + BN_EPS);
        oa[col] = g[col] * r;
        oc[col] = b[col] - g[col] * m * r;
    }
}

// ================= head =================
__global__ void __launch_bounds__(64) head1(
    const float* __restrict__ pooled, const float* __restrict__ pa, const float* __restrict__ pc,
    const float* __restrict__ fcW, const float* __restrict__ fcb,
    const float* __restrict__ feats,
    const float* __restrict__ cW1, const float* __restrict__ cb1,
    const float* __restrict__ cW2, const float* __restrict__ cb2,
    const float* __restrict__ fW1, const float* __restrict__ fb1,
    float* __restrict__ h1out) {
    int g = blockIdx.x;
    int j = threadIdx.x;
    __shared__ float cat[DLAT + 8];
    float o = fcb[j];
    const float* pr = pooled + (size_t)g * DH;
    for (int k = 0; k < DH; k++) o += (pr[k] * pa[k] + pc[k]) * fcW[k * DLAT + j];
    cat[j] = o;
    if (j < 8) {
        float c1[8];
#pragma unroll
        for (int i = 0; i < 8; i++) {
            float a = cb1[i];
#pragma unroll
            for (int m = 0; m < NCOND; m++) a += feats[g * NCOND + m] * cW1[m * 8 + i];
            c1[i] = fmaxf(a, 0.f);
        }
        float o2 = cb2[j];
#pragma unroll
        for (int i = 0; i < 8; i++) o2 += c1[i] * cW2[i * 8 + j];
        cat[DLAT + j] = o2;
    }
    __syncthreads();
    float h = fb1[j];
    for (int k = 0; k < DLAT + 8; k++) h += cat[k] * fW1[k * DLAT + j];
    h1out[(size_t)g * DLAT + j] = leaky(h);
}

__global__ void __launch_bounds__(64) head2(
    const float* __restrict__ h1, const float* __restrict__ fa, const float* __restrict__ fc,
    const float* __restrict__ fW2, const float* __restrict__ fb2,
    float* __restrict__ out) {
    int g = blockIdx.x;
    int j = threadIdx.x;
    __shared__ float hn[DLAT];
    hn[j] = h1[(size_t)g * DLAT + j] * fa[j] + fc[j];
    __syncthreads();
    float o = fb2[j];
    for (int k = 0; k < DLAT; k++) o += hn[k] * fW2[k * DLAT + j];
    out[(size_t)g * DLAT + j] = o;
}

// ================= launch =================
extern "C" void kernel_launch(void* const* d_in, const int* in_sizes, int n_in,
                              void* d_out, int out_size) {
    const float* x      = (const float*)d_in[0];
    const int*   ei     = (const int*)d_in[1];
    const int*   batch  = (const int*)d_in[2];
    const float* feats  = (const float*)d_in[3];
    const float* convW1 = (const float*)d_in[4];
    const float* convb1 = (const float*)d_in[5];
    const float* convg1 = (const float*)d_in[6];
    const float* convbb1= (const float*)d_in[7];
    const float* convW2 = (const float*)d_in[8];
    const float* convb2 = (const float*)d_in[9];
    const float* bng    = (const float*)d_in[10];
    const float* bnb    = (const float*)d_in[11];
    const float* fcW    = (const float*)d_in[12];
    const float* fcb    = (const float*)d_in[13];
    const float* cW1    = (const float*)d_in[14];
    const float* cb1    = (const float*)d_in[15];
    const float* cW2    = (const float*)d_in[16];
    const float* cb2    = (const float*)d_in[17];
    const float* fW1    = (const float*)d_in[18];
    const float* fb1    = (const float*)d_in[19];
    const float* fg     = (const float*)d_in[20];
    const float* fb_    = (const float*)d_in[21];
    const float* fW2    = (const float*)d_in[22];
    const float* fb2    = (const float*)d_in[23];
    float* dout = (float*)d_out;

    int nE = in_sizes[1] / 2;
    const int* src = ei;
    const int* dst = ei + nE;
    int M = in_sizes[0] / DH;
    int G = in_sizes[3] / NCOND;

    float *p_h, *p_h2, *p_x, *p_bias, *p_sum, *p_sq, *p_a, *p_c;
    float *p_pool, *p_pa, *p_pc, *p_h1, *p_fa, *p_fc;
    uint4* p_Bpk;
    int *p_cnt, *p_rowptr, *p_bsum, *p_bscan, *p_csr;
    cudaGetSymbolAddress((void**)&p_h, g_h);
    cudaGetSymbolAddress((void**)&p_h2, g_h2);
    cudaGetSymbolAddress((void**)&p_x, g_x);
    cudaGetSymbolAddress((void**)&p_Bpk, g_Bpk);
    cudaGetSymbolAddress((void**)&p_bias, g_bias);
    cudaGetSymbolAddress((void**)&p_cnt, g_cnt);
    cudaGetSymbolAddress((void**)&p_rowptr, g_rowptr);
    cudaGetSymbolAddress((void**)&p_bsum, g_bsum);
    cudaGetSymbolAddress((void**)&p_bscan, g_bscan);
    cudaGetSymbolAddress((void**)&p_csr, g_csr);
    cudaGetSymbolAddress((void**)&p_sum, g_sum);
    cudaGetSymbolAddress((void**)&p_sq, g_sumsq);
    cudaGetSymbolAddress((void**)&p_a, g_a);
    cudaGetSymbolAddress((void**)&p_c, g_c);
    cudaGetSymbolAddress((void**)&p_pool, g_pooled);
    cudaGetSymbolAddress((void**)&p_pa, g_pa);
    cudaGetSymbolAddress((void**)&p_pc, g_pc);
    cudaGetSymbolAddress((void**)&p_h1, g_h1);
    cudaGetSymbolAddress((void**)&p_fa, g_fa);
    cudaGetSymbolAddress((void**)&p_fc, g_fc);

    cudaFuncSetAttribute(gemm1_stats, cudaFuncAttributeMaxDynamicSharedMemorySize, GEMM_SMEM);
    cudaFuncSetAttribute(gemm2_pool, cudaFuncAttributeMaxDynamicSharedMemorySize, GEMM_SMEM);

    // ---- CSR build ----
    zerok<<<(N_NODES / 4 + 255) / 256, 256>>>((float4*)p_cnt, N_NODES / 4);
    hist_k<<<(nE + 255) / 256, 256>>>(dst, p_cnt, nE);
    int nb = (M + 1023) / 1024;
    scan_block<<<nb, 1024>>>(p_cnt, p_rowptr, p_bsum, M);
    scan_sums<<<1, 128>>>(p_bsum, p_bscan, nb);
    add_off<<<(M + 255) / 256, 256>>>(p_rowptr, p_bscan, p_cnt, M, nE);
    scatter_k<<<(nE + 255) / 256, 256>>>(src, dst, p_cnt, p_csr, nE);

    // ---- zero stats + pooled once ----
    zerok<<<1, 64>>>((float4*)p_sum, DH / 4);
    zerok<<<1, 64>>>((float4*)p_sq, DH / 4);
    zerok<<<(N_GRAPHS * DH / 4 + 255) / 256, 256>>>((float4*)p_pool, N_GRAPHS * DH / 4);

    int gemmGrid = (M + 127) / 128;
    const float* xcur = x;
    for (int l = 0; l < 3; l++) {
        gather_f32<<<(M + 7) / 8, 256>>>(xcur, p_rowptr, p_csr, p_h, M);
        wprep2<<<DH, DH>>>(convW1 + (size_t)l * DH * DH, convb1 + l * DH,
                           nullptr, nullptr, p_Bpk, p_bias, 0);
        gemm1_stats<<<gemmGrid, 256, GEMM_SMEM>>>(
            (const float4*)p_h, p_Bpk, p_bias, p_h2, p_sum, p_sq, M);
        bn_prep<<<1, DH>>>(p_sum, p_sq, (float)M, convg1 + l * DH, convbb1 + l * DH, p_a, p_c, DH);
        wprep2<<<DH, DH>>>(convW2 + (size_t)l * DH * DH, convb2 + l * DH,
                           p_a, p_c, p_Bpk, p_bias, 1);
        gemm2_pool<<<gemmGrid, 256, GEMM_SMEM>>>(
            (const float4*)p_h2, p_Bpk, p_bias, p_x, batch, p_pool, M, (l == 2) ? 1 : 0);
        xcur = p_x;
    }

    colstats<<<DH, 256>>>(p_pool, G, DH, bng, bnb, p_pa, p_pc);
    head1<<<G, 64>>>(p_pool, p_pa, p_pc, fcW, fcb, feats, cW1, cb1, cW2, cb2, fW1, fb1, p_h1);
    colstats<<<DLAT, 256>>>(p_h1, G, DLAT, fg, fb_, p_fa, p_fc);
    head2<<<G, 64>>>(p_h1, p_fa, p_fc, fW2, fb2, dout);
}

// round 7
// speedup vs baseline: 1.6521x; 1.2120x over previous
#include <cuda_runtime.h>
#include <cuda_bf16.h>
#include <cstdint>

#define N_NODES 100000
#define N_EDGESC 1600000
#define N_GRAPHS 512
#define DH 128
#define DLAT 64
#define NCOND 7
#define BN_EPS 1e-5f

// ================= scratch (device globals) =================
// bf16 hi/lo planes: each row = 64 uint32 (bf16x2 pairs over 128 cols)
__device__ uint32_t g_ah[N_NODES * 64];   // gather out hi
__device__ uint32_t g_al[N_NODES * 64];   // gather out lo
__device__ uint32_t g_hh[N_NODES * 64];   // GEMM1 out hi
__device__ uint32_t g_hl[N_NODES * 64];   // GEMM1 out lo
__device__ uint32_t g_xh[N_NODES * 64];   // GEMM2 out hi (layer output)
__device__ uint32_t g_xl[N_NODES * 64];   // GEMM2 out lo
__device__ uint4 g_Bpk[128 * 32];         // fragment-packed weights (bf16 hi/lo)
__device__ float g_bias[DH];
__device__ int g_cnt[N_NODES];
__device__ int g_rowptr[N_NODES + 1];
__device__ int g_bsum[128];
__device__ int g_bscan[128];
__device__ int g_csr[N_EDGESC];
__device__ float g_sum[DH];
__device__ float g_sumsq[DH];
__device__ float g_a[DH];
__device__ float g_c[DH];
__device__ float g_pooled[N_GRAPHS * DH];
__device__ float g_pa[DH];
__device__ float g_pc[DH];
__device__ float g_h1[N_GRAPHS * DLAT];
__device__ float g_fa[DLAT];
__device__ float g_fc[DLAT];

// ================= helpers =================
__device__ __forceinline__ float leaky(float x) { return fmaxf(x, 0.2f * x); }
__device__ __forceinline__ void red_add_v2(float* p, float a, float b) {
    asm volatile("red.global.add.v2.f32 [%0], {%1,%2};"
                 :: "l"(p), "f"(a), "f"(b) : "memory");
}
__device__ __forceinline__ uint32_t bf2bits(__nv_bfloat162 v) {
    return *reinterpret_cast<uint32_t*>(&v);
}
__device__ __forceinline__ __nv_bfloat162 bits2bf2(uint32_t v) {
    return *reinterpret_cast<__nv_bfloat162*>(&v);
}
__device__ __forceinline__ float4 planes2f4(uint2 h, uint2 l) {
    float2 fh0 = __bfloat1622float2(bits2bf2(h.x));
    float2 fh1 = __bfloat1622float2(bits2bf2(h.y));
    float2 fl0 = __bfloat1622float2(bits2bf2(l.x));
    float2 fl1 = __bfloat1622float2(bits2bf2(l.y));
    return make_float4(fh0.x + fl0.x, fh0.y + fl0.y, fh1.x + fl1.x, fh1.y + fl1.y);
}
__device__ __forceinline__ void split_store(uint2* oh, uint2* ol, size_t idx, float4 v) {
    __nv_bfloat162 H0 = __floats2bfloat162_rn(v.x, v.y);
    __nv_bfloat162 H1 = __floats2bfloat162_rn(v.z, v.w);
    float2 f0 = __bfloat1622float2(H0), f1 = __bfloat1622float2(H1);
    __nv_bfloat162 L0 = __floats2bfloat162_rn(v.x - f0.x, v.y - f0.y);
    __nv_bfloat162 L1 = __floats2bfloat162_rn(v.z - f1.x, v.w - f1.y);
    oh[idx] = make_uint2(bf2bits(H0), bf2bits(H1));
    ol[idx] = make_uint2(bf2bits(L0), bf2bits(L1));
}
__device__ __forceinline__ void mma_bf16(float* d, uint32_t a0, uint32_t a1,
                                         uint32_t a2, uint32_t a3,
                                         uint32_t b0, uint32_t b1) {
    asm volatile(
        "mma.sync.aligned.m16n8k16.row.col.f32.bf16.bf16.f32 "
        "{%0,%1,%2,%3}, {%4,%5,%6,%7}, {%8,%9}, {%0,%1,%2,%3};"
        : "+f"(d[0]), "+f"(d[1]), "+f"(d[2]), "+f"(d[3])
        : "r"(a0), "r"(a1), "r"(a2), "r"(a3), "r"(b0), "r"(b1));
}

// ================= zero =================
__global__ void zerok(float4* p, int n4) {
    int i = blockIdx.x * blockDim.x + threadIdx.x;
    if (i < n4) p[i] = make_float4(0.f, 0.f, 0.f, 0.f);
}

// ================= CSR build =================
__global__ void hist_k(const int* __restrict__ dst, int* __restrict__ cnt, int nE) {
    int i = blockIdx.x * blockDim.x + threadIdx.x;
    if (i < nE) atomicAdd(&cnt[dst[i]], 1);
}
__global__ void scan_block(const int* __restrict__ cnt, int* __restrict__ excl,
                           int* __restrict__ bsum, int n) {
    __shared__ int sm[1024];
    int i = blockIdx.x * 1024 + threadIdx.x;
    int v = (i < n) ? cnt[i] : 0;
    sm[threadIdx.x] = v;
    __syncthreads();
    for (int off = 1; off < 1024; off <<= 1) {
        int t = (threadIdx.x >= off) ? sm[threadIdx.x - off] : 0;
        __syncthreads();
        sm[threadIdx.x] += t;
        __syncthreads();
    }
    if (i < n) excl[i] = sm[threadIdx.x] - v;
    if (threadIdx.x == 1023) bsum[blockIdx.x] = sm[1023];
}
__global__ void scan_sums(const int* __restrict__ bsum, int* __restrict__ bscan, int nb) {
    __shared__ int sm[128];
    int t = threadIdx.x;
    int v = (t < nb) ? bsum[t] : 0;
    sm[t] = v;
    __syncthreads();
    for (int off = 1; off < 128; off <<= 1) {
        int u = (t >= off) ? sm[t - off] : 0;
        __syncthreads();
        sm[t] += u;
        __syncthreads();
    }
    if (t < nb) bscan[t] = sm[t] - v;
}
__global__ void add_off(int* __restrict__ rowptr, const int* __restrict__ bscan,
                        int* __restrict__ cursor, int n, int nE) {
    int i = blockIdx.x * blockDim.x + threadIdx.x;
    if (i < n) {
        int v = rowptr[i] + bscan[i >> 10];
        rowptr[i] = v;
        cursor[i] = v;
    }
    if (i == 0) rowptr[n] = nE;
}
__global__ void scatter_k(const int* __restrict__ src, const int* __restrict__ dst,
                          int* __restrict__ cursor, int* __restrict__ csr, int nE) {
    int i = blockIdx.x * blockDim.x + threadIdx.x;
    if (i < nE) {
        int pos = atomicAdd(&cursor[dst[i]], 1);
        csr[pos] = src[i];
    }
}

// ================= gather: h = x[node] + sum_nb x[nb]; out = bf16 hi/lo planes =================
__global__ void __launch_bounds__(256) gather_split(
    const float4* __restrict__ xf, const uint2* __restrict__ xh, const uint2* __restrict__ xl,
    const int* __restrict__ rowptr, const int* __restrict__ csr,
    uint2* __restrict__ oh, uint2* __restrict__ ol, int M, int splitIn) {
    int node = blockIdx.x * 8 + (threadIdx.x >> 5);
    if (node >= M) return;
    int lane = threadIdx.x & 31;
    float4 acc;
    int e0 = __ldg(rowptr + node), e1 = __ldg(rowptr + node + 1);
    if (!splitIn) {
        acc = __ldg(xf + (size_t)node * 32 + lane);
        int e = e0;
        for (; e + 4 <= e1; e += 4) {
            int s0 = __ldg(csr + e), s1 = __ldg(csr + e + 1);
            int s2 = __ldg(csr + e + 2), s3 = __ldg(csr + e + 3);
            float4 v0 = __ldg(xf + (size_t)s0 * 32 + lane);
            float4 v1 = __ldg(xf + (size_t)s1 * 32 + lane);
            float4 v2 = __ldg(xf + (size_t)s2 * 32 + lane);
            float4 v3 = __ldg(xf + (size_t)s3 * 32 + lane);
            acc.x += v0.x + v1.x + v2.x + v3.x;
            acc.y += v0.y + v1.y + v2.y + v3.y;
            acc.z += v0.z + v1.z + v2.z + v3.z;
            acc.w += v0.w + v1.w + v2.w + v3.w;
        }
        for (; e < e1; e++) {
            int s = __ldg(csr + e);
            float4 v = __ldg(xf + (size_t)s * 32 + lane);
            acc.x += v.x; acc.y += v.y; acc.z += v.z; acc.w += v.w;
        }
    } else {
        acc = planes2f4(__ldg(xh + (size_t)node * 32 + lane),
                        __ldg(xl + (size_t)node * 32 + lane));
        int e = e0;
        for (; e + 4 <= e1; e += 4) {
            int s0 = __ldg(csr + e), s1 = __ldg(csr + e + 1);
            int s2 = __ldg(csr + e + 2), s3 = __ldg(csr + e + 3);
            float4 v0 = planes2f4(__ldg(xh + (size_t)s0 * 32 + lane), __ldg(xl + (size_t)s0 * 32 + lane));
            float4 v1 = planes2f4(__ldg(xh + (size_t)s1 * 32 + lane), __ldg(xl + (size_t)s1 * 32 + lane));
            float4 v2 = planes2f4(__ldg(xh + (size_t)s2 * 32 + lane), __ldg(xl + (size_t)s2 * 32 + lane));
            float4 v3 = planes2f4(__ldg(xh + (size_t)s3 * 32 + lane), __ldg(xl + (size_t)s3 * 32 + lane));
            acc.x += v0.x + v1.x + v2.x + v3.x;
            acc.y += v0.y + v1.y + v2.y + v3.y;
            acc.z += v0.z + v1.z + v2.z + v3.z;
            acc.w += v0.w + v1.w + v2.w + v3.w;
        }
        for (; e < e1; e++) {
            int s = __ldg(csr + e);
            float4 v = planes2f4(__ldg(xh + (size_t)s * 32 + lane), __ldg(xl + (size_t)s * 32 + lane));
            acc.x += v.x; acc.y += v.y; acc.z += v.z; acc.w += v.w;
        }
    }
    split_store(oh, ol, (size_t)node * 32 + lane, acc);
}

// ================= weight prep: bf16 hi/lo fragment packing + folded bias =================
// frag layout per (ks 0..7, t 0..15, lane 0..31): uint4 = (bh0, bh1, bl0, bl1)
// b0 covers k = ks*16 + 2*qid + {0,1}; b1 covers k = ks*16 + 8 + 2*qid + {0,1}; n = t*8 + gid
__global__ void __launch_bounds__(128) wprep2(
    const float* __restrict__ W, const float* __restrict__ bvec,
    const float* __restrict__ a, const float* __restrict__ c,
    uint4* __restrict__ Bpk, float* __restrict__ bout, int hasAff) {
    int n = blockIdx.x, k = threadIdx.x;
    float w = W[k * DH + n];
    float ws = hasAff ? a[k] * w : w;
    __nv_bfloat16 hi = __float2bfloat16(ws);
    __nv_bfloat16 lo = __float2bfloat16(ws - __bfloat162float(hi));
    int ks = k >> 4, kr = k & 15;
    int slot = kr >> 3;           // b0 or b1
    int qid = (kr & 7) >> 1;
    int half = kr & 1;
    int t = n >> 3, gid = n & 7;
    int lane = gid * 4 + qid;
    __nv_bfloat16* p = reinterpret_cast<__nv_bfloat16*>(Bpk) +
                       ((size_t)(ks * 16 + t) * 32 + lane) * 8;
    p[slot * 2 + half] = hi;       // words 0,1 = (bh0, bh1)
    p[4 + slot * 2 + half] = lo;   // words 2,3 = (bl0, bl1)
    __shared__ float red[DH];
    red[k] = hasAff ? c[k] * w : 0.f;
    __syncthreads();
    for (int off = 64; off > 0; off >>= 1) {
        if (k < off) red[k] += red[k + off];
        __syncthreads();
    }
    if (k == 0) bout[n] = bvec[n] + red[0];
}

// ================= smem layout for GEMMs =================
#define ASW 68                          // uint32 words per A-plane row (padded)
#define SM_AL_OFF 34816                 // 128*68*4
#define SM_B_OFF 69632                  // 2 planes
#define SM_BIAS_OFF 135168              // 69632 + 65536
#define GEMM_SMEM 135680

// ================= GEMM mainloop (3xBF16, m16n8k16) =================
__device__ __forceinline__ void gemm_mainloop(
    const uint4* __restrict__ Ah, const uint4* __restrict__ Al,
    const uint4* __restrict__ Bpk, const float* __restrict__ bias,
    uint32_t* Ash, uint32_t* Asl, uint4* Bs, float* sb,
    int tid, int row0, int M, float acc[16][4]) {
    if (tid < 128) sb[tid] = bias[tid];
#pragma unroll
    for (int it = 0; it < 8; it++) {
        int idx = it * 256 + tid;
        int r = idx >> 4, q = idx & 15;
        int gr = row0 + r;
        uint4 vh = make_uint4(0u, 0u, 0u, 0u), vl = make_uint4(0u, 0u, 0u, 0u);
        if (gr < M) {
            vh = __ldg(Ah + (size_t)gr * 16 + q);
            vl = __ldg(Al + (size_t)gr * 16 + q);
        }
        *(uint4*)(Ash + r * ASW + q * 4) = vh;
        *(uint4*)(Asl + r * ASW + q * 4) = vl;
    }
#pragma unroll
    for (int it = 0; it < 16; it++) Bs[it * 256 + tid] = __ldg(Bpk + it * 256 + tid);
    __syncthreads();

    int warp = tid >> 5, lane = tid & 31;
    int m0 = warp * 16;
    int gid = lane >> 2, qid = lane & 3;
#pragma unroll
    for (int t = 0; t < 16; t++)
#pragma unroll
        for (int j = 0; j < 4; j++) acc[t][j] = 0.f;

    const uint32_t* ar0h = Ash + (m0 + gid) * ASW;
    const uint32_t* ar1h = Ash + (m0 + gid + 8) * ASW;
    const uint32_t* ar0l = Asl + (m0 + gid) * ASW;
    const uint32_t* ar1l = Asl + (m0 + gid + 8) * ASW;
#pragma unroll
    for (int ks = 0; ks < 8; ks++) {
        int kb = ks * 8 + qid;
        uint32_t a0h = ar0h[kb], a1h = ar1h[kb], a2h = ar0h[kb + 4], a3h = ar1h[kb + 4];
        uint32_t a0l = ar0l[kb], a1l = ar1l[kb], a2l = ar0l[kb + 4], a3l = ar1l[kb + 4];
        const uint4* bp = Bs + ks * 512 + lane;
#pragma unroll
        for (int t = 0; t < 16; t++) {
            uint4 bv = bp[t * 32];
            mma_bf16(acc[t], a0h, a1h, a2h, a3h, bv.x, bv.y);  // ah*bh
            mma_bf16(acc[t], a0h, a1h, a2h, a3h, bv.z, bv.w);  // ah*bl
            mma_bf16(acc[t], a0l, a1l, a2l, a3l, bv.x, bv.y);  // al*bh
        }
    }
}

// ================= GEMM1: + leaky + split-plane out + fused column stats =================
__global__ void __launch_bounds__(256, 1) gemm1_stats(
    const uint4* __restrict__ Ah, const uint4* __restrict__ Al,
    const uint4* __restrict__ Bpk, const float* __restrict__ bias,
    uint32_t* __restrict__ outH, uint32_t* __restrict__ outL,
    float* __restrict__ gsum, float* __restrict__ gsq, int M) {
    extern __shared__ char smem[];
    uint32_t* Ash = (uint32_t*)smem;
    uint32_t* Asl = (uint32_t*)(smem + SM_AL_OFF);
    uint4* Bs = (uint4*)(smem + SM_B_OFF);
    float* sb = (float*)(smem + SM_BIAS_OFF);
    int tid = threadIdx.x;
    int warp = tid >> 5, lane = tid & 31;
    int row0 = blockIdx.x << 7;
    float acc[16][4];
    gemm_mainloop(Ah, Al, Bpk, bias, Ash, Asl, Bs, sb, tid, row0, M, acc);

    int gid = lane >> 2, qid = lane & 3;
    int r0 = row0 + warp * 16 + gid;
    int r1 = r0 + 8;
    float cs[32], cq[32];
#pragma unroll
    for (int t = 0; t < 16; t++) {
        int c = t * 8 + qid * 2;
        float b0 = sb[c], b1 = sb[c + 1];
        float v00 = 0.f, v01 = 0.f, v10 = 0.f, v11 = 0.f;
        if (r0 < M) {
            v00 = leaky(acc[t][0] + b0);
            v01 = leaky(acc[t][1] + b1);
            __nv_bfloat162 H = __floats2bfloat162_rn(v00, v01);
            float2 f = __bfloat1622float2(H);
            __nv_bfloat162 L = __floats2bfloat162_rn(v00 - f.x, v01 - f.y);
            outH[(size_t)r0 * 64 + t * 4 + qid] = bf2bits(H);
            outL[(size_t)r0 * 64 + t * 4 + qid] = bf2bits(L);
        }
        if (r1 < M) {
            v10 = leaky(acc[t][2] + b0);
            v11 = leaky(acc[t][3] + b1);
            __nv_bfloat162 H = __floats2bfloat162_rn(v10, v11);
            float2 f = __bfloat1622float2(H);
            __nv_bfloat162 L = __floats2bfloat162_rn(v10 - f.x, v11 - f.y);
            outH[(size_t)r1 * 64 + t * 4 + qid] = bf2bits(H);
            outL[(size_t)r1 * 64 + t * 4 + qid] = bf2bits(L);
        }
        cs[2 * t] = v00 + v10;
        cs[2 * t + 1] = v01 + v11;
        cq[2 * t] = v00 * v00 + v10 * v10;
        cq[2 * t + 1] = v01 * v01 + v11 * v11;
    }

    __syncthreads();  // mainloop smem reads done; reuse as stats scratch
    float* ssum = (float*)smem;          // [64][128]
    float* ssq = (float*)smem + 8192;    // [64][128]
    int slot = warp * 8 + gid;
#pragma unroll
    for (int t = 0; t < 16; t++) {
        int c = t * 8 + qid * 2;
        ssum[slot * 128 + c] = cs[2 * t];
        ssum[slot * 128 + c + 1] = cs[2 * t + 1];
        ssq[slot * 128 + c] = cq[2 * t];
        ssq[slot * 128 + c + 1] = cq[2 * t + 1];
    }
    __syncthreads();
    if (tid < 128) {
        float s = 0.f;
#pragma unroll
        for (int w = 0; w < 64; w++) s += ssum[w * 128 + tid];
        atomicAdd(&gsum[tid], s);
    } else {
        int c = tid - 128;
        float q = 0.f;
#pragma unroll
        for (int w = 0; w < 64; w++) q += ssq[w * 128 + c];
        atomicAdd(&gsq[c], q);
    }
}

// ================= GEMM2: + leaky; mode0: split-plane store; mode1: pool-only =================
__global__ void __launch_bounds__(256, 1) gemm2_pool(
    const uint4* __restrict__ Ah, const uint4* __restrict__ Al,
    const uint4* __restrict__ Bpk, const float* __restrict__ bias,
    uint32_t* __restrict__ outH, uint32_t* __restrict__ outL,
    const int* __restrict__ batch, float* __restrict__ pooled,
    int M, int doPool) {
    extern __shared__ char smem[];
    uint32_t* Ash = (uint32_t*)smem;
    uint32_t* Asl = (uint32_t*)(smem + SM_AL_OFF);
    uint4* Bs = (uint4*)(smem + SM_B_OFF);
    float* sb = (float*)(smem + SM_BIAS_OFF);
    int tid = threadIdx.x;
    int warp = tid >> 5, lane = tid & 31;
    int row0 = blockIdx.x << 7;
    float acc[16][4];
    gemm_mainloop(Ah, Al, Bpk, bias, Ash, Asl, Bs, sb, tid, row0, M, acc);

    int gid = lane >> 2, qid = lane & 3;
    int r0 = row0 + warp * 16 + gid;
    int r1 = r0 + 8;
    if (!doPool) {
#pragma unroll
        for (int t = 0; t < 16; t++) {
            int c = t * 8 + qid * 2;
            float b0 = sb[c], b1 = sb[c + 1];
            if (r0 < M) {
                float v0 = leaky(acc[t][0] + b0), v1 = leaky(acc[t][1] + b1);
                __nv_bfloat162 H = __floats2bfloat162_rn(v0, v1);
                float2 f = __bfloat1622float2(H);
                __nv_bfloat162 L = __floats2bfloat162_rn(v0 - f.x, v1 - f.y);
                outH[(size_t)r0 * 64 + t * 4 + qid] = bf2bits(H);
                outL[(size_t)r0 * 64 + t * 4 + qid] = bf2bits(L);
            }
            if (r1 < M) {
                float v0 = leaky(acc[t][2] + b0), v1 = leaky(acc[t][3] + b1);
                __nv_bfloat162 H = __floats2bfloat162_rn(v0, v1);
                float2 f = __bfloat1622float2(H);
                __nv_bfloat162 L = __floats2bfloat162_rn(v0 - f.x, v1 - f.y);
                outH[(size_t)r1 * 64 + t * 4 + qid] = bf2bits(H);
                outL[(size_t)r1 * 64 + t * 4 + qid] = bf2bits(L);
            }
        }
    } else {
        int b0g = (r0 < M) ? __ldg(batch + r0) : 0;
        int b1g = (r1 < M) ? __ldg(batch + r1) : 0;
#pragma unroll
        for (int t = 0; t < 16; t++) {
            int c = t * 8 + qid * 2;
            float b0 = sb[c], b1 = sb[c + 1];
            if (r0 < M)
                red_add_v2(pooled + (size_t)b0g * DH + c,
                           leaky(acc[t][0] + b0), leaky(acc[t][1] + b1));
            if (r1 < M)
                red_add_v2(pooled + (size_t)b1g * DH + c,
                           leaky(acc[t][2] + b0), leaky(acc[t][3] + b1));
        }
    }
}

// ================= sums -> folded BN affine (also zeroes accumulators) =================
__global__ void bn_prep(float* __restrict__ sum, float* __restrict__ sumsq,
                        float n, const float* __restrict__ g, const float* __restrict__ b,
                        float* __restrict__ oa, float* __restrict__ oc, int D) {
    int c = threadIdx.x;
    if (c < D) {
        float m = sum[c] / n;
        float v = sumsq[c] / n - m * m;
        float r = rsqrtf(v + BN_EPS);
        oa[c] = g[c] * r;
        oc[c] = b[c] - g[c] * m * r;
        sum[c] = 0.f;
        sumsq[c] = 0.f;
    }
}

// ================= small column stats (pooled / h1) =================
__global__ void colstats(const float* __restrict__ data, int rows, int cols,
                         const float* __restrict__ g, const float* __restrict__ b,
                         float* __restrict__ oa, float* __restrict__ oc) {
    int col = blockIdx.x;
    int t = threadIdx.x;
    float s = 0.f, q = 0.f;
    for (int r = t; r < rows; r += blockDim.x) {
        float v = data[(size_t)r * cols + col];
        s += v; q += v * v;
    }
    __shared__ float ss[256], qq[256];
    ss[t] = s; qq[t] = q;
    __syncthreads();
    for (int off = 128; off > 0; off >>= 1) {
        if (t < off) { ss[t] += ss[t + off]; qq[t] += qq[t + off]; }
        __syncthreads();
    }
    if (t == 0) {
        float m = ss[0] / rows;
        float v = qq[0] / rows - m * m;
        float r = rsqrtf(v + BN_EPS);
        oa[col] = g[col] * r;
        oc[col] = b[col] - g[col] * m * r;
    }
}

// ================= head =================
__global__ void __launch_bounds__(64) head1(
    const float* __restrict__ pooled, const float* __restrict__ pa, const float* __restrict__ pc,
    const float* __restrict__ fcW, const float* __restrict__ fcb,
    const float* __restrict__ feats,
    const float* __restrict__ cW1, const float* __restrict__ cb1,
    const float* __restrict__ cW2, const float* __restrict__ cb2,
    const float* __restrict__ fW1, const float* __restrict__ fb1,
    float* __restrict__ h1out) {
    int g = blockIdx.x;
    int j = threadIdx.x;
    __shared__ float cat[DLAT + 8];
    float o = fcb[j];
    const float* pr = pooled + (size_t)g * DH;
    for (int k = 0; k < DH; k++) o += (pr[k] * pa[k] + pc[k]) * fcW[k * DLAT + j];
    cat[j] = o;
    if (j < 8) {
        float c1[8];
#pragma unroll
        for (int i = 0; i < 8; i++) {
            float a = cb1[i];
#pragma unroll
            for (int m = 0; m < NCOND; m++) a += feats[g * NCOND + m] * cW1[m * 8 + i];
            c1[i] = fmaxf(a, 0.f);
        }
        float o2 = cb2[j];
#pragma unroll
        for (int i = 0; i < 8; i++) o2 += c1[i] * cW2[i * 8 + j];
        cat[DLAT + j] = o2;
    }
    __syncthreads();
    float h = fb1[j];
    for (int k = 0; k < DLAT + 8; k++) h += cat[k] * fW1[k * DLAT + j];
    h1out[(size_t)g * DLAT + j] = leaky(h);
}

__global__ void __launch_bounds__(64) head2(
    const float* __restrict__ h1, const float* __restrict__ fa, const float* __restrict__ fc,
    const float* __restrict__ fW2, const float* __restrict__ fb2,
    float* __restrict__ out) {
    int g = blockIdx.x;
    int j = threadIdx.x;
    __shared__ float hn[DLAT];
    hn[j] = h1[(size_t)g * DLAT + j] * fa[j] + fc[j];
    __syncthreads();
    float o = fb2[j];
    for (int k = 0; k < DLAT; k++) o += hn[k] * fW2[k * DLAT + j];
    out[(size_t)g * DLAT + j] = o;
}

// ================= launch =================
extern "C" void kernel_launch(void* const* d_in, const int* in_sizes, int n_in,
                              void* d_out, int out_size) {
    const float* x      = (const float*)d_in[0];
    const int*   ei     = (const int*)d_in[1];
    const int*   batch  = (const int*)d_in[2];
    const float* feats  = (const float*)d_in[3];
    const float* convW1 = (const float*)d_in[4];
    const float* convb1 = (const float*)d_in[5];
    const float* convg1 = (const float*)d_in[6];
    const float* convbb1= (const float*)d_in[7];
    const float* convW2 = (const float*)d_in[8];
    const float* convb2 = (const float*)d_in[9];
    const float* bng    = (const float*)d_in[10];
    const float* bnb    = (const float*)d_in[11];
    const float* fcW    = (const float*)d_in[12];
    const float* fcb    = (const float*)d_in[13];
    const float* cW1    = (const float*)d_in[14];
    const float* cb1    = (const float*)d_in[15];
    const float* cW2    = (const float*)d_in[16];
    const float* cb2    = (const float*)d_in[17];
    const float* fW1    = (const float*)d_in[18];
    const float* fb1    = (const float*)d_in[19];
    const float* fg     = (const float*)d_in[20];
    const float* fb_    = (const float*)d_in[21];
    const float* fW2    = (const float*)d_in[22];
    const float* fb2    = (const float*)d_in[23];
    float* dout = (float*)d_out;

    int nE = in_sizes[1] / 2;
    const int* src = ei;
    const int* dst = ei + nE;
    int M = in_sizes[0] / DH;
    int G = in_sizes[3] / NCOND;

    uint32_t *p_ah, *p_al, *p_hh, *p_hl, *p_xh, *p_xl;
    float *p_bias, *p_sum, *p_sq, *p_a, *p_c, *p_pool, *p_pa, *p_pc, *p_h1, *p_fa, *p_fc;
    uint4* p_Bpk;
    int *p_cnt, *p_rowptr, *p_bsum, *p_bscan, *p_csr;
    cudaGetSymbolAddress((void**)&p_ah, g_ah);
    cudaGetSymbolAddress((void**)&p_al, g_al);
    cudaGetSymbolAddress((void**)&p_hh, g_hh);
    cudaGetSymbolAddress((void**)&p_hl, g_hl);
    cudaGetSymbolAddress((void**)&p_xh, g_xh);
    cudaGetSymbolAddress((void**)&p_xl, g_xl);
    cudaGetSymbolAddress((void**)&p_Bpk, g_Bpk);
    cudaGetSymbolAddress((void**)&p_bias, g_bias);
    cudaGetSymbolAddress((void**)&p_cnt, g_cnt);
    cudaGetSymbolAddress((void**)&p_rowptr, g_rowptr);
    cudaGetSymbolAddress((void**)&p_bsum, g_bsum);
    cudaGetSymbolAddress((void**)&p_bscan, g_bscan);
    cudaGetSymbolAddress((void**)&p_csr, g_csr);
    cudaGetSymbolAddress((void**)&p_sum, g_sum);
    cudaGetSymbolAddress((void**)&p_sq, g_sumsq);
    cudaGetSymbolAddress((void**)&p_a, g_a);
    cudaGetSymbolAddress((void**)&p_c, g_c);
    cudaGetSymbolAddress((void**)&p_pool, g_pooled);
    cudaGetSymbolAddress((void**)&p_pa, g_pa);
    cudaGetSymbolAddress((void**)&p_pc, g_pc);
    cudaGetSymbolAddress((void**)&p_h1, g_h1);
    cudaGetSymbolAddress((void**)&p_fa, g_fa);
    cudaGetSymbolAddress((void**)&p_fc, g_fc);

    cudaFuncSetAttribute(gemm1_stats, cudaFuncAttributeMaxDynamicSharedMemorySize, GEMM_SMEM);
    cudaFuncSetAttribute(gemm2_pool, cudaFuncAttributeMaxDynamicSharedMemorySize, GEMM_SMEM);

    // ---- CSR build ----
    zerok<<<(N_NODES / 4 + 255) / 256, 256>>>((float4*)p_cnt, N_NODES / 4);
    hist_k<<<(nE + 255) / 256, 256>>>(dst, p_cnt, nE);
    int nb = (M + 1023) / 1024;
    scan_block<<<nb, 1024>>>(p_cnt, p_rowptr, p_bsum, M);
    scan_sums<<<1, 128>>>(p_bsum, p_bscan, nb);
    add_off<<<(M + 255) / 256, 256>>>(p_rowptr, p_bscan, p_cnt, M, nE);
    scatter_k<<<(nE + 255) / 256, 256>>>(src, dst, p_cnt, p_csr, nE);

    // ---- zero stats + pooled once ----
    zerok<<<1, 64>>>((float4*)p_sum, DH / 4);
    zerok<<<1, 64>>>((float4*)p_sq, DH / 4);
    zerok<<<(N_GRAPHS * DH / 4 + 255) / 256, 256>>>((float4*)p_pool, N_GRAPHS * DH / 4);

    int gemmGrid = (M + 127) / 128;
    for (int l = 0; l < 3; l++) {
        gather_split<<<(M + 7) / 8, 256>>>(
            (const float4*)x, (const uint2*)p_xh, (const uint2*)p_xl,
            p_rowptr, p_csr, (uint2*)p_ah, (uint2*)p_al, M, (l == 0) ? 0 : 1);
        wprep2<<<DH, DH>>>(convW1 + (size_t)l * DH * DH, convb1 + l * DH,
                           nullptr, nullptr, p_Bpk, p_bias, 0);
        gemm1_stats<<<gemmGrid, 256, GEMM_SMEM>>>(
            (const uint4*)p_ah, (const uint4*)p_al, p_Bpk, p_bias,
            p_hh, p_hl, p_sum, p_sq, M);
        bn_prep<<<1, DH>>>(p_sum, p_sq, (float)M, convg1 + l * DH, convbb1 + l * DH, p_a, p_c, DH);
        wprep2<<<DH, DH>>>(convW2 + (size_t)l * DH * DH, convb2 + l * DH,
                           p_a, p_c, p_Bpk, p_bias, 1);
        gemm2_pool<<<gemmGrid, 256, GEMM_SMEM>>>(
            (const uint4*)p_hh, (const uint4*)p_hl, p_Bpk, p_bias,
            p_xh, p_xl, batch, p_pool, M, (l == 2) ? 1 : 0);
    }

    colstats<<<DH, 256>>>(p_pool, G, DH, bng, bnb, p_pa, p_pc);
    head1<<<G, 64>>>(p_pool, p_pa, p_pc, fcW, fcb, feats, cW1, cb1, cW2, cb2, fW1, fb1, p_h1);
    colstats<<<DLAT, 256>>>(p_h1, G, DLAT, fg, fb_, p_fa, p_fc);
    head2<<<G, 64>>>(p_h1, p_fa, p_fc, fW2, fb2, dout);
}

// round 8
// speedup vs baseline: 1.6828x; 1.0186x over previous
#include <cuda_runtime.h>
#include <cuda_bf16.h>
#include <cstdint>

#define N_NODES 100000
#define N_EDGESC 1600000
#define N_GRAPHS 512
#define DH 128
#define DLAT 64
#define NCOND 7
#define BN_EPS 1e-5f

// ================= scratch (device globals) =================
// interleaved hi/lo rows: 32 uint4 per row; uint4 g = (hi(4g,4g+1), hi(4g+2,4g+3), lo(4g,4g+1), lo(4g+2,4g+3))
__device__ uint4 g_a[N_NODES * 32];     // gather out
__device__ uint4 g_h[N_NODES * 32];     // GEMM1 out
__device__ uint4 g_x[N_NODES * 32];     // GEMM2 out (layer output)
__device__ uint4 g_Bpk[128 * 32];       // fragment-packed weights (bf16 hi/lo)
__device__ float g_bias[DH];
__device__ int g_cnt[N_NODES];
__device__ int g_rowptr[N_NODES + 1];
__device__ int g_bsum[128];
__device__ int g_bscan[128];
__device__ int g_csr[N_EDGESC];
__device__ float g_sum[DH];
__device__ float g_sumsq[DH];
__device__ float g_a2[DH];
__device__ float g_c2[DH];
__device__ float g_pooled[N_GRAPHS * DH];
__device__ float g_pa[DH];
__device__ float g_pc[DH];
__device__ float g_h1[N_GRAPHS * DLAT];
__device__ float g_fa[DLAT];
__device__ float g_fc[DLAT];

// ================= helpers =================
__device__ __forceinline__ float leaky(float x) { return fmaxf(x, 0.2f * x); }
__device__ __forceinline__ void red_add_v2(float* p, float a, float b) {
    asm volatile("red.global.add.v2.f32 [%0], {%1,%2};"
                 :: "l"(p), "f"(a), "f"(b) : "memory");
}
__device__ __forceinline__ uint32_t bf2bits(__nv_bfloat162 v) {
    return *reinterpret_cast<uint32_t*>(&v);
}
__device__ __forceinline__ __nv_bfloat162 bits2bf2(uint32_t v) {
    return *reinterpret_cast<__nv_bfloat162*>(&v);
}
// decode interleaved uint4 -> 4 fp32 cols
__device__ __forceinline__ float4 dec4(uint4 v) {
    float2 h0 = __bfloat1622float2(bits2bf2(v.x));
    float2 h1 = __bfloat1622float2(bits2bf2(v.y));
    float2 l0 = __bfloat1622float2(bits2bf2(v.z));
    float2 l1 = __bfloat1622float2(bits2bf2(v.w));
    return make_float4(h0.x + l0.x, h0.y + l0.y, h1.x + l1.x, h1.y + l1.y);
}
// encode 4 fp32 cols -> interleaved uint4
__device__ __forceinline__ uint4 enc4(float4 a) {
    __nv_bfloat162 H0 = __floats2bfloat162_rn(a.x, a.y);
    __nv_bfloat162 H1 = __floats2bfloat162_rn(a.z, a.w);
    float2 f0 = __bfloat1622float2(H0), f1 = __bfloat1622float2(H1);
    __nv_bfloat162 L0 = __floats2bfloat162_rn(a.x - f0.x, a.y - f0.y);
    __nv_bfloat162 L1 = __floats2bfloat162_rn(a.z - f1.x, a.w - f1.y);
    return make_uint4(bf2bits(H0), bf2bits(H1), bf2bits(L0), bf2bits(L1));
}
__device__ __forceinline__ void mma_bf16(float* d, uint32_t a0, uint32_t a1,
                                         uint32_t a2, uint32_t a3,
                                         uint32_t b0, uint32_t b1) {
    asm volatile(
        "mma.sync.aligned.m16n8k16.row.col.f32.bf16.bf16.f32 "
        "{%0,%1,%2,%3}, {%4,%5,%6,%7}, {%8,%9}, {%0,%1,%2,%3};"
        : "+f"(d[0]), "+f"(d[1]), "+f"(d[2]), "+f"(d[3])
        : "r"(a0), "r"(a1), "r"(a2), "r"(a3), "r"(b0), "r"(b1));
}

// ================= zero =================
__global__ void zerok(float4* p, int n4) {
    int i = blockIdx.x * blockDim.x + threadIdx.x;
    if (i < n4) p[i] = make_float4(0.f, 0.f, 0.f, 0.f);
}
// zero sum, sq, pooled in one launch
__global__ void zero3(float4* sum4, float4* sq4, float4* pool4, int pool4n) {
    int i = blockIdx.x * blockDim.x + threadIdx.x;
    if (i < pool4n) pool4[i] = make_float4(0.f, 0.f, 0.f, 0.f);
    if (i < DH / 4) {
        sum4[i] = make_float4(0.f, 0.f, 0.f, 0.f);
        sq4[i] = make_float4(0.f, 0.f, 0.f, 0.f);
    }
}

// ================= CSR build =================
__global__ void hist_k(const int* __restrict__ dst, int* __restrict__ cnt, int nE) {
    int i = blockIdx.x * blockDim.x + threadIdx.x;
    if (i < nE) atomicAdd(&cnt[dst[i]], 1);
}
__global__ void scan_block(const int* __restrict__ cnt, int* __restrict__ excl,
                           int* __restrict__ bsum, int n) {
    __shared__ int sm[1024];
    int i = blockIdx.x * 1024 + threadIdx.x;
    int v = (i < n) ? cnt[i] : 0;
    sm[threadIdx.x] = v;
    __syncthreads();
    for (int off = 1; off < 1024; off <<= 1) {
        int t = (threadIdx.x >= off) ? sm[threadIdx.x - off] : 0;
        __syncthreads();
        sm[threadIdx.x] += t;
        __syncthreads();
    }
    if (i < n) excl[i] = sm[threadIdx.x] - v;
    if (threadIdx.x == 1023) bsum[blockIdx.x] = sm[1023];
}
__global__ void scan_sums(const int* __restrict__ bsum, int* __restrict__ bscan, int nb) {
    __shared__ int sm[128];
    int t = threadIdx.x;
    int v = (t < nb) ? bsum[t] : 0;
    sm[t] = v;
    __syncthreads();
    for (int off = 1; off < 128; off <<= 1) {
        int u = (t >= off) ? sm[t - off] : 0;
        __syncthreads();
        sm[t] += u;
        __syncthreads();
    }
    if (t < nb) bscan[t] = sm[t] - v;
}
__global__ void add_off(int* __restrict__ rowptr, const int* __restrict__ bscan,
                        int* __restrict__ cursor, int n, int nE) {
    int i = blockIdx.x * blockDim.x + threadIdx.x;
    if (i < n) {
        int v = rowptr[i] + bscan[i >> 10];
        rowptr[i] = v;
        cursor[i] = v;
    }
    if (i == 0) rowptr[n] = nE;
}
__global__ void scatter_k(const int* __restrict__ src, const int* __restrict__ dst,
                          int* __restrict__ cursor, int* __restrict__ csr, int nE) {
    int i = blockIdx.x * blockDim.x + threadIdx.x;
    if (i < nE) {
        int pos = atomicAdd(&cursor[dst[i]], 1);
        csr[pos] = src[i];
    }
}

// ================= gather: h = x[node] + sum_nb x[nb]; interleaved in/out =================
__global__ void __launch_bounds__(256) gather_i(
    const float4* __restrict__ xf, const uint4* __restrict__ xc,
    const int* __restrict__ rowptr, const int* __restrict__ csr,
    uint4* __restrict__ out, int M, int splitIn) {
    int node = blockIdx.x * 8 + (threadIdx.x >> 5);
    if (node >= M) return;
    int lane = threadIdx.x & 31;
    int e0 = __ldg(rowptr + node), e1 = __ldg(rowptr + node + 1);
    float4 acc;
    if (!splitIn) {
        acc = __ldg(xf + (size_t)node * 32 + lane);
        int e = e0;
        for (; e + 8 <= e1; e += 8) {
            int s[8];
#pragma unroll
            for (int u = 0; u < 8; u++) s[u] = __ldg(csr + e + u);
            float4 v[8];
#pragma unroll
            for (int u = 0; u < 8; u++) v[u] = __ldg(xf + (size_t)s[u] * 32 + lane);
#pragma unroll
            for (int u = 0; u < 8; u++) {
                acc.x += v[u].x; acc.y += v[u].y; acc.z += v[u].z; acc.w += v[u].w;
            }
        }
        for (; e < e1; e++) {
            int s = __ldg(csr + e);
            float4 v = __ldg(xf + (size_t)s * 32 + lane);
            acc.x += v.x; acc.y += v.y; acc.z += v.z; acc.w += v.w;
        }
    } else {
        acc = dec4(__ldg(xc + (size_t)node * 32 + lane));
        int e = e0;
        for (; e + 8 <= e1; e += 8) {
            int s[8];
#pragma unroll
            for (int u = 0; u < 8; u++) s[u] = __ldg(csr + e + u);
            uint4 w[8];
#pragma unroll
            for (int u = 0; u < 8; u++) w[u] = __ldg(xc + (size_t)s[u] * 32 + lane);
#pragma unroll
            for (int u = 0; u < 8; u++) {
                float4 v = dec4(w[u]);
                acc.x += v.x; acc.y += v.y; acc.z += v.z; acc.w += v.w;
            }
        }
        for (; e < e1; e++) {
            int s = __ldg(csr + e);
            float4 v = dec4(__ldg(xc + (size_t)s * 32 + lane));
            acc.x += v.x; acc.y += v.y; acc.z += v.z; acc.w += v.w;
        }
    }
    out[(size_t)node * 32 + lane] = enc4(acc);
}

// ================= weight prep: bf16 hi/lo fragment packing + folded bias =================
__global__ void __launch_bounds__(128) wprep2(
    const float* __restrict__ W, const float* __restrict__ bvec,
    const float* __restrict__ a, const float* __restrict__ c,
    uint4* __restrict__ Bpk, float* __restrict__ bout, int hasAff) {
    int n = blockIdx.x, k = threadIdx.x;
    float w = W[k * DH + n];
    float ws = hasAff ? a[k] * w : w;
    __nv_bfloat16 hi = __float2bfloat16(ws);
    __nv_bfloat16 lo = __float2bfloat16(ws - __bfloat162float(hi));
    int ks = k >> 4, kr = k & 15;
    int slot = kr >> 3;
    int qid = (kr & 7) >> 1;
    int half = kr & 1;
    int t = n >> 3, gid = n & 7;
    int lane = gid * 4 + qid;
    __nv_bfloat16* p = reinterpret_cast<__nv_bfloat16*>(Bpk) +
                       ((size_t)(ks * 16 + t) * 32 + lane) * 8;
    p[slot * 2 + half] = hi;
    p[4 + slot * 2 + half] = lo;
    __shared__ float red[DH];
    red[k] = hasAff ? c[k] * w : 0.f;
    __syncthreads();
    for (int off = 64; off > 0; off >>= 1) {
        if (k < off) red[k] += red[k + off];
        __syncthreads();
    }
    if (k == 0) bout[n] = bvec[n] + red[0];
}

// ================= smem layout for GEMMs =================
#define ASW 68                          // uint32 words per A-plane row (padded)
#define SM_AL_OFF 34816                 // 128*68*4
#define SM_B_OFF 69632
#define SM_BIAS_OFF 135168
#define GEMM_SMEM 135680

// ================= GEMM mainloop (3xBF16, m16n8k16) =================
__device__ __forceinline__ void gemm_mainloop(
    const uint4* __restrict__ A, const uint4* __restrict__ Bpk,
    const float* __restrict__ bias,
    uint32_t* Ash, uint32_t* Asl, uint4* Bs, float* sb,
    int tid, int row0, int M, float acc[16][4]) {
    if (tid < 128) sb[tid] = bias[tid];
#pragma unroll
    for (int it = 0; it < 16; it++) {
        int idx = it * 256 + tid;
        int r = idx >> 5, g = idx & 31;
        int gr = row0 + r;
        uint4 v = make_uint4(0u, 0u, 0u, 0u);
        if (gr < M) v = __ldg(A + (size_t)gr * 32 + g);
        *(uint2*)(Ash + r * ASW + 2 * g) = make_uint2(v.x, v.y);
        *(uint2*)(Asl + r * ASW + 2 * g) = make_uint2(v.z, v.w);
    }
#pragma unroll
    for (int it = 0; it < 16; it++) Bs[it * 256 + tid] = __ldg(Bpk + it * 256 + tid);
    __syncthreads();

    int warp = tid >> 5, lane = tid & 31;
    int m0 = warp * 16;
    int gid = lane >> 2, qid = lane & 3;
#pragma unroll
    for (int t = 0; t < 16; t++)
#pragma unroll
        for (int j = 0; j < 4; j++) acc[t][j] = 0.f;

    const uint32_t* ar0h = Ash + (m0 + gid) * ASW;
    const uint32_t* ar1h = Ash + (m0 + gid + 8) * ASW;
    const uint32_t* ar0l = Asl + (m0 + gid) * ASW;
    const uint32_t* ar1l = Asl + (m0 + gid + 8) * ASW;
#pragma unroll
    for (int ks = 0; ks < 8; ks++) {
        int kb = ks * 8 + qid;
        uint32_t a0h = ar0h[kb], a1h = ar1h[kb], a2h = ar0h[kb + 4], a3h = ar1h[kb + 4];
        uint32_t a0l = ar0l[kb], a1l = ar1l[kb], a2l = ar0l[kb + 4], a3l = ar1l[kb + 4];
        const uint4* bp = Bs + ks * 512 + lane;
#pragma unroll
        for (int t = 0; t < 16; t++) {
            uint4 bv = bp[t * 32];
            mma_bf16(acc[t], a0h, a1h, a2h, a3h, bv.x, bv.y);  // ah*bh
            mma_bf16(acc[t], a0h, a1h, a2h, a3h, bv.z, bv.w);  // ah*bl
            mma_bf16(acc[t], a0l, a1l, a2l, a3l, bv.x, bv.y);  // al*bh
        }
    }
}

// epilogue pack: 2 cols (v0,v1) -> hi word + lo word, interleaved row store
__device__ __forceinline__ void store_pair(uint32_t* orow, int j, float v0, float v1) {
    __nv_bfloat162 H = __floats2bfloat162_rn(v0, v1);
    float2 f = __bfloat1622float2(H);
    __nv_bfloat162 L = __floats2bfloat162_rn(v0 - f.x, v1 - f.y);
    orow[(j >> 1) * 4 + (j & 1)] = bf2bits(H);
    orow[(j >> 1) * 4 + 2 + (j & 1)] = bf2bits(L);
}

// ================= GEMM1: + leaky + interleaved out + fused column stats =================
__global__ void __launch_bounds__(256, 1) gemm1_stats(
    const uint4* __restrict__ A, const uint4* __restrict__ Bpk,
    const float* __restrict__ bias, uint32_t* __restrict__ out,
    float* __restrict__ gsum, float* __restrict__ gsq, int M) {
    extern __shared__ char smem[];
    uint32_t* Ash = (uint32_t*)smem;
    uint32_t* Asl = (uint32_t*)(smem + SM_AL_OFF);
    uint4* Bs = (uint4*)(smem + SM_B_OFF);
    float* sb = (float*)(smem + SM_BIAS_OFF);
    int tid = threadIdx.x;
    int warp = tid >> 5, lane = tid & 31;
    int row0 = blockIdx.x << 7;
    float acc[16][4];
    gemm_mainloop(A, Bpk, bias, Ash, Asl, Bs, sb, tid, row0, M, acc);

    int gid = lane >> 2, qid = lane & 3;
    int r0 = row0 + warp * 16 + gid;
    int r1 = r0 + 8;
    uint32_t* orow0 = out + (size_t)r0 * 128;
    uint32_t* orow1 = out + (size_t)r1 * 128;
    float cs[32], cq[32];
#pragma unroll
    for (int t = 0; t < 16; t++) {
        int c = t * 8 + qid * 2;
        int j = t * 4 + qid;
        float b0 = sb[c], b1 = sb[c + 1];
        float v00 = 0.f, v01 = 0.f, v10 = 0.f, v11 = 0.f;
        if (r0 < M) {
            v00 = leaky(acc[t][0] + b0);
            v01 = leaky(acc[t][1] + b1);
            store_pair(orow0, j, v00, v01);
        }
        if (r1 < M) {
            v10 = leaky(acc[t][2] + b0);
            v11 = leaky(acc[t][3] + b1);
            store_pair(orow1, j, v10, v11);
        }
        cs[2 * t] = v00 + v10;
        cs[2 * t + 1] = v01 + v11;
        cq[2 * t] = v00 * v00 + v10 * v10;
        cq[2 * t + 1] = v01 * v01 + v11 * v11;
    }

    __syncthreads();
    float* ssum = (float*)smem;
    float* ssq = (float*)smem + 8192;
    int slot = warp * 8 + gid;
#pragma unroll
    for (int t = 0; t < 16; t++) {
        int c = t * 8 + qid * 2;
        ssum[slot * 128 + c] = cs[2 * t];
        ssum[slot * 128 + c + 1] = cs[2 * t + 1];
        ssq[slot * 128 + c] = cq[2 * t];
        ssq[slot * 128 + c + 1] = cq[2 * t + 1];
    }
    __syncthreads();
    if (tid < 128) {
        float s = 0.f;
#pragma unroll
        for (int w = 0; w < 64; w++) s += ssum[w * 128 + tid];
        atomicAdd(&gsum[tid], s);
    } else {
        int c = tid - 128;
        float q = 0.f;
#pragma unroll
        for (int w = 0; w < 64; w++) q += ssq[w * 128 + c];
        atomicAdd(&gsq[c], q);
    }
}

// ================= GEMM2: + leaky; mode0: interleaved store; mode1: pool-only =================
__global__ void __launch_bounds__(256, 1) gemm2_pool(
    const uint4* __restrict__ A, const uint4* __restrict__ Bpk,
    const float* __restrict__ bias, uint32_t* __restrict__ out,
    const int* __restrict__ batch, float* __restrict__ pooled,
    int M, int doPool) {
    extern __shared__ char smem[];
    uint32_t* Ash = (uint32_t*)smem;
    uint32_t* Asl = (uint32_t*)(smem + SM_AL_OFF);
    uint4* Bs = (uint4*)(smem + SM_B_OFF);
    float* sb = (float*)(smem + SM_BIAS_OFF);
    int tid = threadIdx.x;
    int warp = tid >> 5, lane = tid & 31;
    int row0 = blockIdx.x << 7;
    float acc[16][4];
    gemm_mainloop(A, Bpk, bias, Ash, Asl, Bs, sb, tid, row0, M, acc);

    int gid = lane >> 2, qid = lane & 3;
    int r0 = row0 + warp * 16 + gid;
    int r1 = r0 + 8;
    if (!doPool) {
        uint32_t* orow0 = out + (size_t)r0 * 128;
        uint32_t* orow1 = out + (size_t)r1 * 128;
#pragma unroll
        for (int t = 0; t < 16; t++) {
            int c = t * 8 + qid * 2;
            int j = t * 4 + qid;
            float b0 = sb[c], b1 = sb[c + 1];
            if (r0 < M)
                store_pair(orow0, j, leaky(acc[t][0] + b0), leaky(acc[t][1] + b1));
            if (r1 < M)
                store_pair(orow1, j, leaky(acc[t][2] + b0), leaky(acc[t][3] + b1));
        }
    } else {
        int b0g = (r0 < M) ? __ldg(batch + r0) : 0;
        int b1g = (r1 < M) ? __ldg(batch + r1) : 0;
#pragma unroll
        for (int t = 0; t < 16; t++) {
            int c = t * 8 + qid * 2;
            float b0 = sb[c], b1 = sb[c + 1];
            if (r0 < M)
                red_add_v2(pooled + (size_t)b0g * DH + c,
                           leaky(acc[t][0] + b0), leaky(acc[t][1] + b1));
            if (r1 < M)
                red_add_v2(pooled + (size_t)b1g * DH + c,
                           leaky(acc[t][2] + b0), leaky(acc[t][3] + b1));
        }
    }
}

// ================= sums -> folded BN affine (also zeroes accumulators) =================
__global__ void bn_prep(float* __restrict__ sum, float* __restrict__ sumsq,
                        float n, const float* __restrict__ g, const float* __restrict__ b,
                        float* __restrict__ oa, float* __restrict__ oc, int D) {
    int c = threadIdx.x;
    if (c < D) {
        float m = sum[c] / n;
        float v = sumsq[c] / n - m * m;
        float r = rsqrtf(v + BN_EPS);
        oa[c] = g[c] * r;
        oc[c] = b[c] - g[c] * m * r;
        sum[c] = 0.f;
        sumsq[c] = 0.f;
    }
}

// ================= small column stats (pooled / h1) =================
__global__ void colstats(const float* __restrict__ data, int rows, int cols,
                         const float* __restrict__ g, const float* __restrict__ b,
                         float* __restrict__ oa, float* __restrict__ oc) {
    int col = blockIdx.x;
    int t = threadIdx.x;
    float s = 0.f, q = 0.f;
    for (int r = t; r < rows; r += blockDim.x) {
        float v = data[(size_t)r * cols + col];
        s += v; q += v * v;
    }
    __shared__ float ss[256], qq[256];
    ss[t] = s; qq[t] = q;
    __syncthreads();
    for (int off = 128; off > 0; off >>= 1) {
        if (t < off) { ss[t] += ss[t + off]; qq[t] += qq[t + off]; }
        __syncthreads();
    }
    if (t == 0) {
        float m = ss[0] / rows;
        float v = qq[0] / rows - m * m;
        float r = rsqrtf(v + BN_EPS);
        oa[col] = g[col] * r;
        oc[col] = b[col] - g[col] * m * r;
    }
}

// ================= head =================
__global__ void __launch_bounds__(64) head1(
    const float* __restrict__ pooled, const float* __restrict__ pa, const float* __restrict__ pc,
    const float* __restrict__ fcW, const float* __restrict__ fcb,
    const float* __restrict__ feats,
    const float* __restrict__ cW1, const float* __restrict__ cb1,
    const float* __restrict__ cW2, const float* __restrict__ cb2,
    const float* __restrict__ fW1, const float* __restrict__ fb1,
    float* __restrict__ h1out) {
    int g = blockIdx.x;
    int j = threadIdx.x;
    __shared__ float cat[DLAT + 8];
    float o = fcb[j];
    const float* pr = pooled + (size_t)g * DH;
    for (int k = 0; k < DH; k++) o += (pr[k] * pa[k] + pc[k]) * fcW[k * DLAT + j];
    cat[j] = o;
    if (j < 8) {
        float c1[8];
#pragma unroll
        for (int i = 0; i < 8; i++) {
            float a = cb1[i];
#pragma unroll
            for (int m = 0; m < NCOND; m++) a += feats[g * NCOND + m] * cW1[m * 8 + i];
            c1[i] = fmaxf(a, 0.f);
        }
        float o2 = cb2[j];
#pragma unroll
        for (int i = 0; i < 8; i++) o2 += c1[i] * cW2[i * 8 + j];
        cat[DLAT + j] = o2;
    }
    __syncthreads();
    float h = fb1[j];
    for (int k = 0; k < DLAT + 8; k++) h += cat[k] * fW1[k * DLAT + j];
    h1out[(size_t)g * DLAT + j] = leaky(h);
}

__global__ void __launch_bounds__(64) head2(
    const float* __restrict__ h1, const float* __restrict__ fa, const float* __restrict__ fc,
    const float* __restrict__ fW2, const float* __restrict__ fb2,
    float* __restrict__ out) {
    int g = blockIdx.x;
    int j = threadIdx.x;
    __shared__ float hn[DLAT];
    hn[j] = h1[(size_t)g * DLAT + j] * fa[j] + fc[j];
    __syncthreads();
    float o = fb2[j];
    for (int k = 0; k < DLAT; k++) o += hn[k] * fW2[k * DLAT + j];
    out[(size_t)g * DLAT + j] = o;
}

// ================= launch =================
extern "C" void kernel_launch(void* const* d_in, const int* in_sizes, int n_in,
                              void* d_out, int out_size) {
    const float* x      = (const float*)d_in[0];
    const int*   ei     = (const int*)d_in[1];
    const int*   batch  = (const int*)d_in[2];
    const float* feats  = (const float*)d_in[3];
    const float* convW1 = (const float*)d_in[4];
    const float* convb1 = (const float*)d_in[5];
    const float* convg1 = (const float*)d_in[6];
    const float* convbb1= (const float*)d_in[7];
    const float* convW2 = (const float*)d_in[8];
    const float* convb2 = (const float*)d_in[9];
    const float* bng    = (const float*)d_in[10];
    const float* bnb    = (const float*)d_in[11];
    const float* fcW    = (const float*)d_in[12];
    const float* fcb    = (const float*)d_in[13];
    const float* cW1    = (const float*)d_in[14];
    const float* cb1    = (const float*)d_in[15];
    const float* cW2    = (const float*)d_in[16];
    const float* cb2    = (const float*)d_in[17];
    const float* fW1    = (const float*)d_in[18];
    const float* fb1    = (const float*)d_in[19];
    const float* fg     = (const float*)d_in[20];
    const float* fb_    = (const float*)d_in[21];
    const float* fW2    = (const float*)d_in[22];
    const float* fb2    = (const float*)d_in[23];
    float* dout = (float*)d_out;

    int nE = in_sizes[1] / 2;
    const int* src = ei;
    const int* dst = ei + nE;
    int M = in_sizes[0] / DH;
    int G = in_sizes[3] / NCOND;

    uint4 *p_a, *p_h, *p_x, *p_Bpk;
    float *p_bias, *p_sum, *p_sq, *p_a2, *p_c2, *p_pool, *p_pa, *p_pc, *p_h1, *p_fa, *p_fc;
    int *p_cnt, *p_rowptr, *p_bsum, *p_bscan, *p_csr;
    cudaGetSymbolAddress((void**)&p_a, g_a);
    cudaGetSymbolAddress((void**)&p_h, g_h);
    cudaGetSymbolAddress((void**)&p_x, g_x);
    cudaGetSymbolAddress((void**)&p_Bpk, g_Bpk);
    cudaGetSymbolAddress((void**)&p_bias, g_bias);
    cudaGetSymbolAddress((void**)&p_cnt, g_cnt);
    cudaGetSymbolAddress((void**)&p_rowptr, g_rowptr);
    cudaGetSymbolAddress((void**)&p_bsum, g_bsum);
    cudaGetSymbolAddress((void**)&p_bscan, g_bscan);
    cudaGetSymbolAddress((void**)&p_csr, g_csr);
    cudaGetSymbolAddress((void**)&p_sum, g_sum);
    cudaGetSymbolAddress((void**)&p_sq, g_sumsq);
    cudaGetSymbolAddress((void**)&p_a2, g_a2);
    cudaGetSymbolAddress((void**)&p_c2, g_c2);
    cudaGetSymbolAddress((void**)&p_pool, g_pooled);
    cudaGetSymbolAddress((void**)&p_pa, g_pa);
    cudaGetSymbolAddress((void**)&p_pc, g_pc);
    cudaGetSymbolAddress((void**)&p_h1, g_h1);
    cudaGetSymbolAddress((void**)&p_fa, g_fa);
    cudaGetSymbolAddress((void**)&p_fc, g_fc);

    cudaFuncSetAttribute(gemm1_stats, cudaFuncAttributeMaxDynamicSharedMemorySize, GEMM_SMEM);
    cudaFuncSetAttribute(gemm2_pool, cudaFuncAttributeMaxDynamicSharedMemorySize, GEMM_SMEM);

    // ---- CSR build ----
    zerok<<<(N_NODES / 4 + 255) / 256, 256>>>((float4*)p_cnt, N_NODES / 4);
    hist_k<<<(nE + 255) / 256, 256>>>(dst, p_cnt, nE);
    int nb = (M + 1023) / 1024;
    scan_block<<<nb, 1024>>>(p_cnt, p_rowptr, p_bsum, M);
    scan_sums<<<1, 128>>>(p_bsum, p_bscan, nb);
    add_off<<<(M + 255) / 256, 256>>>(p_rowptr, p_bscan, p_cnt, M, nE);
    scatter_k<<<(nE + 255) / 256, 256>>>(src, dst, p_cnt, p_csr, nE);

    // ---- zero stats + pooled in one launch ----
    zero3<<<(N_GRAPHS * DH / 4 + 255) / 256, 256>>>(
        (float4*)p_sum, (float4*)p_sq, (float4*)p_pool, N_GRAPHS * DH / 4);

    int gemmGrid = (M + 127) / 128;
    for (int l = 0; l < 3; l++) {
        gather_i<<<(M + 7) / 8, 256>>>(
            (const float4*)x, (const uint4*)p_x, p_rowptr, p_csr, p_a, M, (l == 0) ? 0 : 1);
        wprep2<<<DH, DH>>>(convW1 + (size_t)l * DH * DH, convb1 + l * DH,
                           nullptr, nullptr, p_Bpk, p_bias, 0);
        gemm1_stats<<<gemmGrid, 256, GEMM_SMEM>>>(
            p_a, p_Bpk, p_bias, (uint32_t*)p_h, p_sum, p_sq, M);
        bn_prep<<<1, DH>>>(p_sum, p_sq, (float)M, convg1 + l * DH, convbb1 + l * DH,
                           p_a2, p_c2, DH);
        wprep2<<<DH, DH>>>(convW2 + (size_t)l * DH * DH, convb2 + l * DH,
                           p_a2, p_c2, p_Bpk, p_bias, 1);
        gemm2_pool<<<gemmGrid, 256, GEMM_SMEM>>>(
            p_h, p_Bpk, p_bias, (uint32_t*)p_x, batch, p_pool, M, (l == 2) ? 1 : 0);
    }

    colstats<<<DH, 256>>>(p_pool, G, DH, bng, bnb, p_pa, p_pc);
    head1<<<G, 64>>>(p_pool, p_pa, p_pc, fcW, fcb, feats, cW1, cb1, cW2, cb2, fW1, fb1, p_h1);
    colstats<<<DLAT, 256>>>(p_h1, G, DLAT, fg, fb_, p_fa, p_fc);
    head2<<<G, 64>>>(p_h1, p_fa, p_fc, fW2, fb2, dout);
}

// round 9
// speedup vs baseline: 1.7493x; 1.0395x over previous
#include <cuda_runtime.h>
#include <cuda_bf16.h>
#include <cstdint>

#define N_NODES 100000
#define N_EDGESC 1600000
#define N_GRAPHS 512
#define DH 128
#define DLAT 64
#define NCOND 7
#define BN_EPS 1e-5f

// ================= scratch (device globals) =================
// interleaved hi/lo rows: 32 uint4 per row; uint4 g = (hi(4g,4g+1), hi(4g+2,4g+3), lo(4g,4g+1), lo(4g+2,4g+3))
__device__ uint4 g_a[N_NODES * 32];     // gather out
__device__ uint4 g_h[N_NODES * 32];     // GEMM1 out
__device__ uint4 g_x[N_NODES * 32];     // GEMM2 out (layer output)
__device__ uint4 g_Bpk[128 * 32];       // fragment-packed weights (bf16 hi/lo)
__device__ float g_bias[DH];
__device__ int g_cnt[N_NODES];
__device__ int g_rowptr[N_NODES + 1];
__device__ int g_bsum[128];
__device__ int g_bscan[128];
__device__ int g_csr[N_EDGESC];
__device__ float g_sum[DH];
__device__ float g_sumsq[DH];
__device__ float g_a2[DH];
__device__ float g_c2[DH];
__device__ float g_pooled[N_GRAPHS * DH];
__device__ float g_pa[DH];
__device__ float g_pc[DH];
__device__ float g_h1[N_GRAPHS * DLAT];
__device__ float g_fa[DLAT];
__device__ float g_fc[DLAT];

// ================= helpers =================
__device__ __forceinline__ float leaky(float x) { return fmaxf(x, 0.2f * x); }
__device__ __forceinline__ void red_add_v2(float* p, float a, float b) {
    asm volatile("red.global.add.v2.f32 [%0], {%1,%2};"
                 :: "l"(p), "f"(a), "f"(b) : "memory");
}
__device__ __forceinline__ uint32_t bf2bits(__nv_bfloat162 v) {
    return *reinterpret_cast<uint32_t*>(&v);
}
__device__ __forceinline__ __nv_bfloat162 bits2bf2(uint32_t v) {
    return *reinterpret_cast<__nv_bfloat162*>(&v);
}
__device__ __forceinline__ float4 dec4(uint4 v) {
    float2 h0 = __bfloat1622float2(bits2bf2(v.x));
    float2 h1 = __bfloat1622float2(bits2bf2(v.y));
    float2 l0 = __bfloat1622float2(bits2bf2(v.z));
    float2 l1 = __bfloat1622float2(bits2bf2(v.w));
    return make_float4(h0.x + l0.x, h0.y + l0.y, h1.x + l1.x, h1.y + l1.y);
}
__device__ __forceinline__ uint4 enc4(float4 a) {
    __nv_bfloat162 H0 = __floats2bfloat162_rn(a.x, a.y);
    __nv_bfloat162 H1 = __floats2bfloat162_rn(a.z, a.w);
    float2 f0 = __bfloat1622float2(H0), f1 = __bfloat1622float2(H1);
    __nv_bfloat162 L0 = __floats2bfloat162_rn(a.x - f0.x, a.y - f0.y);
    __nv_bfloat162 L1 = __floats2bfloat162_rn(a.z - f1.x, a.w - f1.y);
    return make_uint4(bf2bits(H0), bf2bits(H1), bf2bits(L0), bf2bits(L1));
}
__device__ __forceinline__ void mma_bf16(float* d, uint32_t a0, uint32_t a1,
                                         uint32_t a2, uint32_t a3,
                                         uint32_t b0, uint32_t b1) {
    asm volatile(
        "mma.sync.aligned.m16n8k16.row.col.f32.bf16.bf16.f32 "
        "{%0,%1,%2,%3}, {%4,%5,%6,%7}, {%8,%9}, {%0,%1,%2,%3};"
        : "+f"(d[0]), "+f"(d[1]), "+f"(d[2]), "+f"(d[3])
        : "r"(a0), "r"(a1), "r"(a2), "r"(a3), "r"(b0), "r"(b1));
}

// ================= zero =================
__global__ void zerok(float4* p, int n4) {
    int i = blockIdx.x * blockDim.x + threadIdx.x;
    if (i < n4) p[i] = make_float4(0.f, 0.f, 0.f, 0.f);
}
__global__ void zero3(float4* sum4, float4* sq4, float4* pool4, int pool4n) {
    int i = blockIdx.x * blockDim.x + threadIdx.x;
    if (i < pool4n) pool4[i] = make_float4(0.f, 0.f, 0.f, 0.f);
    if (i < DH / 4) {
        sum4[i] = make_float4(0.f, 0.f, 0.f, 0.f);
        sq4[i] = make_float4(0.f, 0.f, 0.f, 0.f);
    }
}

// ================= CSR build =================
__global__ void hist_k(const int* __restrict__ dst, int* __restrict__ cnt, int nE) {
    int i = blockIdx.x * blockDim.x + threadIdx.x;
    if (i < nE) atomicAdd(&cnt[dst[i]], 1);
}
__global__ void scan_block(const int* __restrict__ cnt, int* __restrict__ excl,
                           int* __restrict__ bsum, int n) {
    __shared__ int sm[1024];
    int i = blockIdx.x * 1024 + threadIdx.x;
    int v = (i < n) ? cnt[i] : 0;
    sm[threadIdx.x] = v;
    __syncthreads();
    for (int off = 1; off < 1024; off <<= 1) {
        int t = (threadIdx.x >= off) ? sm[threadIdx.x - off] : 0;
        __syncthreads();
        sm[threadIdx.x] += t;
        __syncthreads();
    }
    if (i < n) excl[i] = sm[threadIdx.x] - v;
    if (threadIdx.x == 1023) bsum[blockIdx.x] = sm[1023];
}
__global__ void scan_sums(const int* __restrict__ bsum, int* __restrict__ bscan, int nb) {
    __shared__ int sm[128];
    int t = threadIdx.x;
    int v = (t < nb) ? bsum[t] : 0;
    sm[t] = v;
    __syncthreads();
    for (int off = 1; off < 128; off <<= 1) {
        int u = (t >= off) ? sm[t - off] : 0;
        __syncthreads();
        sm[t] += u;
        __syncthreads();
    }
    if (t < nb) bscan[t] = sm[t] - v;
}
__global__ void add_off(int* __restrict__ rowptr, const int* __restrict__ bscan,
                        int* __restrict__ cursor, int n, int nE) {
    int i = blockIdx.x * blockDim.x + threadIdx.x;
    if (i < n) {
        int v = rowptr[i] + bscan[i >> 10];
        rowptr[i] = v;
        cursor[i] = v;
    }
    if (i == 0) rowptr[n] = nE;
}
__global__ void scatter_k(const int* __restrict__ src, const int* __restrict__ dst,
                          int* __restrict__ cursor, int* __restrict__ csr, int nE) {
    int i = blockIdx.x * blockDim.x + threadIdx.x;
    if (i < nE) {
        int pos = atomicAdd(&cursor[dst[i]], 1);
        csr[pos] = src[i];
    }
}

// ================= gather: h = x[node] + sum_nb x[nb]; interleaved in/out =================
__global__ void __launch_bounds__(256) gather_i(
    const float4* __restrict__ xf, const uint4* __restrict__ xc,
    const int* __restrict__ rowptr, const int* __restrict__ csr,
    uint4* __restrict__ out, int M, int splitIn) {
    int node = blockIdx.x * 8 + (threadIdx.x >> 5);
    if (node >= M) return;
    int lane = threadIdx.x & 31;
    int e0 = __ldg(rowptr + node), e1 = __ldg(rowptr + node + 1);
    float4 acc;
    if (!splitIn) {
        acc = __ldg(xf + (size_t)node * 32 + lane);
        int e = e0;
        for (; e + 8 <= e1; e += 8) {
            int s[8];
#pragma unroll
            for (int u = 0; u < 8; u++) s[u] = __ldg(csr + e + u);
            float4 v[8];
#pragma unroll
            for (int u = 0; u < 8; u++) v[u] = __ldg(xf + (size_t)s[u] * 32 + lane);
#pragma unroll
            for (int u = 0; u < 8; u++) {
                acc.x += v[u].x; acc.y += v[u].y; acc.z += v[u].z; acc.w += v[u].w;
            }
        }
        for (; e < e1; e++) {
            int s = __ldg(csr + e);
            float4 v = __ldg(xf + (size_t)s * 32 + lane);
            acc.x += v.x; acc.y += v.y; acc.z += v.z; acc.w += v.w;
        }
    } else {
        acc = dec4(__ldg(xc + (size_t)node * 32 + lane));
        int e = e0;
        for (; e + 8 <= e1; e += 8) {
            int s[8];
#pragma unroll
            for (int u = 0; u < 8; u++) s[u] = __ldg(csr + e + u);
            uint4 w[8];
#pragma unroll
            for (int u = 0; u < 8; u++) w[u] = __ldg(xc + (size_t)s[u] * 32 + lane);
#pragma unroll
            for (int u = 0; u < 8; u++) {
                float4 v = dec4(w[u]);
                acc.x += v.x; acc.y += v.y; acc.z += v.z; acc.w += v.w;
            }
        }
        for (; e < e1; e++) {
            int s = __ldg(csr + e);
            float4 v = dec4(__ldg(xc + (size_t)s * 32 + lane));
            acc.x += v.x; acc.y += v.y; acc.z += v.z; acc.w += v.w;
        }
    }
    out[(size_t)node * 32 + lane] = enc4(acc);
}

// ================= weight prep: bf16 hi/lo fragment packing + folded bias =================
__global__ void __launch_bounds__(128) wprep2(
    const float* __restrict__ W, const float* __restrict__ bvec,
    const float* __restrict__ a, const float* __restrict__ c,
    uint4* __restrict__ Bpk, float* __restrict__ bout, int hasAff) {
    int n = blockIdx.x, k = threadIdx.x;
    float w = W[k * DH + n];
    float ws = hasAff ? a[k] * w : w;
    __nv_bfloat16 hi = __float2bfloat16(ws);
    __nv_bfloat16 lo = __float2bfloat16(ws - __bfloat162float(hi));
    int ks = k >> 4, kr = k & 15;
    int slot = kr >> 3;
    int qid = (kr & 7) >> 1;
    int half = kr & 1;
    int t = n >> 3, gid = n & 7;
    int lane = gid * 4 + qid;
    __nv_bfloat16* p = reinterpret_cast<__nv_bfloat16*>(Bpk) +
                       ((size_t)(ks * 16 + t) * 32 + lane) * 8;
    p[slot * 2 + half] = hi;
    p[4 + slot * 2 + half] = lo;
    __shared__ float red[DH];
    red[k] = hasAff ? c[k] * w : 0.f;
    __syncthreads();
    for (int off = 64; off > 0; off >>= 1) {
        if (k < off) red[k] += red[k + off];
        __syncthreads();
    }
    if (k == 0) bout[n] = bvec[n] + red[0];
}

// ================= smem layout for GEMMs (256-row tiles) =================
#define ASW 68                             // uint32 words per A-plane row (padded)
#define A_ROWS 256
#define SM_AL_OFF (A_ROWS * ASW * 4)       // 69632
#define SM_B_OFF (2 * A_ROWS * ASW * 4)    // 139264
#define SM_BIAS_OFF (SM_B_OFF + 65536)     // 204800
#define GEMM_SMEM (SM_BIAS_OFF + 512)      // 205312

// ================= GEMM mainloop (3xBF16, m16n8k16, 2 m-tiles/warp) =================
__device__ __forceinline__ void gemm_mainloop(
    const uint4* __restrict__ A, const uint4* __restrict__ Bpk,
    const float* __restrict__ bias,
    uint32_t* Ash, uint32_t* Asl, uint4* Bs, float* sb,
    int tid, int row0, int M, float acc[2][16][4]) {
    if (tid < 128) sb[tid] = bias[tid];
#pragma unroll
    for (int it = 0; it < 32; it++) {
        int idx = it * 256 + tid;
        int r = idx >> 5, g = idx & 31;
        int gr = row0 + r;
        uint4 v = make_uint4(0u, 0u, 0u, 0u);
        if (gr < M) v = __ldg(A + (size_t)gr * 32 + g);
        *(uint2*)(Ash + r * ASW + 2 * g) = make_uint2(v.x, v.y);
        *(uint2*)(Asl + r * ASW + 2 * g) = make_uint2(v.z, v.w);
    }
#pragma unroll
    for (int it = 0; it < 16; it++) Bs[it * 256 + tid] = __ldg(Bpk + it * 256 + tid);
    __syncthreads();

    int warp = tid >> 5, lane = tid & 31;
    int m0 = warp * 32;
    int gid = lane >> 2, qid = lane & 3;
#pragma unroll
    for (int mt = 0; mt < 2; mt++)
#pragma unroll
        for (int t = 0; t < 16; t++)
#pragma unroll
            for (int j = 0; j < 4; j++) acc[mt][t][j] = 0.f;

    const uint32_t *rh0[2], *rh1[2], *rl0[2], *rl1[2];
#pragma unroll
    for (int mt = 0; mt < 2; mt++) {
        rh0[mt] = Ash + (m0 + 16 * mt + gid) * ASW;
        rh1[mt] = Ash + (m0 + 16 * mt + gid + 8) * ASW;
        rl0[mt] = Asl + (m0 + 16 * mt + gid) * ASW;
        rl1[mt] = Asl + (m0 + 16 * mt + gid + 8) * ASW;
    }
#pragma unroll
    for (int ks = 0; ks < 8; ks++) {
        int kb = ks * 8 + qid;
        uint32_t Ahf[2][4], Alf[2][4];
#pragma unroll
        for (int mt = 0; mt < 2; mt++) {
            Ahf[mt][0] = rh0[mt][kb]; Ahf[mt][1] = rh1[mt][kb];
            Ahf[mt][2] = rh0[mt][kb + 4]; Ahf[mt][3] = rh1[mt][kb + 4];
            Alf[mt][0] = rl0[mt][kb]; Alf[mt][1] = rl1[mt][kb];
            Alf[mt][2] = rl0[mt][kb + 4]; Alf[mt][3] = rl1[mt][kb + 4];
        }
        const uint4* bp = Bs + ks * 512 + lane;
#pragma unroll
        for (int t = 0; t < 16; t++) {
            uint4 bv = bp[t * 32];
#pragma unroll
            for (int mt = 0; mt < 2; mt++) {
                mma_bf16(acc[mt][t], Ahf[mt][0], Ahf[mt][1], Ahf[mt][2], Ahf[mt][3], bv.x, bv.y);
                mma_bf16(acc[mt][t], Ahf[mt][0], Ahf[mt][1], Ahf[mt][2], Ahf[mt][3], bv.z, bv.w);
                mma_bf16(acc[mt][t], Alf[mt][0], Alf[mt][1], Alf[mt][2], Alf[mt][3], bv.x, bv.y);
            }
        }
    }
}

// epilogue pack: 2 cols (v0,v1) -> hi word + lo word, interleaved row store
__device__ __forceinline__ void store_pair(uint32_t* orow, int j, float v0, float v1) {
    __nv_bfloat162 H = __floats2bfloat162_rn(v0, v1);
    float2 f = __bfloat1622float2(H);
    __nv_bfloat162 L = __floats2bfloat162_rn(v0 - f.x, v1 - f.y);
    orow[(j >> 1) * 4 + (j & 1)] = bf2bits(H);
    orow[(j >> 1) * 4 + 2 + (j & 1)] = bf2bits(L);
}

// ================= GEMM1: + leaky + interleaved out + fused column stats =================
__global__ void __launch_bounds__(256, 1) gemm1_stats(
    const uint4* __restrict__ A, const uint4* __restrict__ Bpk,
    const float* __restrict__ bias, uint32_t* __restrict__ out,
    float* __restrict__ gsum, float* __restrict__ gsq, int M) {
    extern __shared__ char smem[];
    uint32_t* Ash = (uint32_t*)smem;
    uint32_t* Asl = (uint32_t*)(smem + SM_AL_OFF);
    uint4* Bs = (uint4*)(smem + SM_B_OFF);
    float* sb = (float*)(smem + SM_BIAS_OFF);
    int tid = threadIdx.x;
    int warp = tid >> 5, lane = tid & 31;
    int row0 = blockIdx.x << 8;
    float acc[2][16][4];
    gemm_mainloop(A, Bpk, bias, Ash, Asl, Bs, sb, tid, row0, M, acc);

    int gid = lane >> 2, qid = lane & 3;
    float cs[32], cq[32];
#pragma unroll
    for (int i = 0; i < 32; i++) { cs[i] = 0.f; cq[i] = 0.f; }
#pragma unroll
    for (int mt = 0; mt < 2; mt++) {
        int r0 = row0 + warp * 32 + 16 * mt + gid;
        int r1 = r0 + 8;
        uint32_t* orow0 = out + (size_t)r0 * 128;
        uint32_t* orow1 = out + (size_t)r1 * 128;
#pragma unroll
        for (int t = 0; t < 16; t++) {
            int c = t * 8 + qid * 2;
            int j = t * 4 + qid;
            float b0 = sb[c], b1 = sb[c + 1];
            float v00 = 0.f, v01 = 0.f, v10 = 0.f, v11 = 0.f;
            if (r0 < M) {
                v00 = leaky(acc[mt][t][0] + b0);
                v01 = leaky(acc[mt][t][1] + b1);
                store_pair(orow0, j, v00, v01);
            }
            if (r1 < M) {
                v10 = leaky(acc[mt][t][2] + b0);
                v11 = leaky(acc[mt][t][3] + b1);
                store_pair(orow1, j, v10, v11);
            }
            cs[2 * t] += v00 + v10;
            cs[2 * t + 1] += v01 + v11;
            cq[2 * t] += v00 * v00 + v10 * v10;
            cq[2 * t + 1] += v01 * v01 + v11 * v11;
        }
    }

    __syncthreads();
    float* ssum = (float*)smem;
    float* ssq = (float*)smem + 8192;
    int slot = warp * 8 + gid;
#pragma unroll
    for (int t = 0; t < 16; t++) {
        int c = t * 8 + qid * 2;
        ssum[slot * 128 + c] = cs[2 * t];
        ssum[slot * 128 + c + 1] = cs[2 * t + 1];
        ssq[slot * 128 + c] = cq[2 * t];
        ssq[slot * 128 + c + 1] = cq[2 * t + 1];
    }
    __syncthreads();
    if (tid < 128) {
        float s = 0.f;
#pragma unroll
        for (int w = 0; w < 64; w++) s += ssum[w * 128 + tid];
        atomicAdd(&gsum[tid], s);
    } else {
        int c = tid - 128;
        float q = 0.f;
#pragma unroll
        for (int w = 0; w < 64; w++) q += ssq[w * 128 + c];
        atomicAdd(&gsq[c], q);
    }
}

// ================= GEMM2: + leaky; mode0: interleaved store; mode1: pool-only =================
__global__ void __launch_bounds__(256, 1) gemm2_pool(
    const uint4* __restrict__ A, const uint4* __restrict__ Bpk,
    const float* __restrict__ bias, uint32_t* __restrict__ out,
    const int* __restrict__ batch, float* __restrict__ pooled,
    int M, int doPool) {
    extern __shared__ char smem[];
    uint32_t* Ash = (uint32_t*)smem;
    uint32_t* Asl = (uint32_t*)(smem + SM_AL_OFF);
    uint4* Bs = (uint4*)(smem + SM_B_OFF);
    float* sb = (float*)(smem + SM_BIAS_OFF);
    int tid = threadIdx.x;
    int warp = tid >> 5, lane = tid & 31;
    int row0 = blockIdx.x << 8;
    float acc[2][16][4];
    gemm_mainloop(A, Bpk, bias, Ash, Asl, Bs, sb, tid, row0, M, acc);

    int gid = lane >> 2, qid = lane & 3;
    if (!doPool) {
#pragma unroll
        for (int mt = 0; mt < 2; mt++) {
            int r0 = row0 + warp * 32 + 16 * mt + gid;
            int r1 = r0 + 8;
            uint32_t* orow0 = out + (size_t)r0 * 128;
            uint32_t* orow1 = out + (size_t)r1 * 128;
#pragma unroll
            for (int t = 0; t < 16; t++) {
                int c = t * 8 + qid * 2;
                int j = t * 4 + qid;
                float b0 = sb[c], b1 = sb[c + 1];
                if (r0 < M)
                    store_pair(orow0, j, leaky(acc[mt][t][0] + b0), leaky(acc[mt][t][1] + b1));
                if (r1 < M)
                    store_pair(orow1, j, leaky(acc[mt][t][2] + b0), leaky(acc[mt][t][3] + b1));
            }
        }
    } else {
#pragma unroll
        for (int mt = 0; mt < 2; mt++) {
            int r0 = row0 + warp * 32 + 16 * mt + gid;
            int r1 = r0 + 8;
            int b0g = (r0 < M) ? __ldg(batch + r0) : 0;
            int b1g = (r1 < M) ? __ldg(batch + r1) : 0;
#pragma unroll
            for (int t = 0; t < 16; t++) {
                int c = t * 8 + qid * 2;
                float b0 = sb[c], b1 = sb[c + 1];
                if (r0 < M)
                    red_add_v2(pooled + (size_t)b0g * DH + c,
                               leaky(acc[mt][t][0] + b0), leaky(acc[mt][t][1] + b1));
                if (r1 < M)
                    red_add_v2(pooled + (size_t)b1g * DH + c,
                               leaky(acc[mt][t][2] + b0), leaky(acc[mt][t][3] + b1));
            }
        }
    }
}

// ================= sums -> folded BN affine (also zeroes accumulators) =================
__global__ void bn_prep(float* __restrict__ sum, float* __restrict__ sumsq,
                        float n, const float* __restrict__ g, const float* __restrict__ b,
                        float* __restrict__ oa, float* __restrict__ oc, int D) {
    int c = threadIdx.x;
    if (c < D) {
        float m = sum[c] / n;
        float v = sumsq[c] / n - m * m;
        float r = rsqrtf(v + BN_EPS);
        oa[c] = g[c] * r;
        oc[c] = b[c] - g[c] * m * r;
        sum[c] = 0.f;
        sumsq[c] = 0.f;
    }
}

// ================= small column stats (pooled / h1) =================
__global__ void colstats(const float* __restrict__ data, int rows, int cols,
                         const float* __restrict__ g, const float* __restrict__ b,
                         float* __restrict__ oa, float* __restrict__ oc) {
    int col = blockIdx.x;
    int t = threadIdx.x;
    float s = 0.f, q = 0.f;
    for (int r = t; r < rows; r += blockDim.x) {
        float v = data[(size_t)r * cols + col];
        s += v; q += v * v;
    }
    __shared__ float ss[256], qq[256];
    ss[t] = s; qq[t] = q;
    __syncthreads();
    for (int off = 128; off > 0; off >>= 1) {
        if (t < off) { ss[t] += ss[t + off]; qq[t] += qq[t + off]; }
        __syncthreads();
    }
    if (t == 0) {
        float m = ss[0] / rows;
        float v = qq[0] / rows - m * m;
        float r = rsqrtf(v + BN_EPS);
        oa[col] = g[col] * r;
        oc[col] = b[col] - g[col] * m * r;
    }
}

// ================= head =================
__global__ void __launch_bounds__(64) head1(
    const float* __restrict__ pooled, const float* __restrict__ pa, const float* __restrict__ pc,
    const float* __restrict__ fcW, const float* __restrict__ fcb,
    const float* __restrict__ feats,
    const float* __restrict__ cW1, const float* __restrict__ cb1,
    const float* __restrict__ cW2, const float* __restrict__ cb2,
    const float* __restrict__ fW1, const float* __restrict__ fb1,
    float* __restrict__ h1out) {
    int g = blockIdx.x;
    int j = threadIdx.x;
    __shared__ float cat[DLAT + 8];
    float o = fcb[j];
    const float* pr = pooled + (size_t)g * DH;
    for (int k = 0; k < DH; k++) o += (pr[k] * pa[k] + pc[k]) * fcW[k * DLAT + j];
    cat[j] = o;
    if (j < 8) {
        float c1[8];
#pragma unroll
        for (int i = 0; i < 8; i++) {
            float a = cb1[i];
#pragma unroll
            for (int m = 0; m < NCOND; m++) a += feats[g * NCOND + m] * cW1[m * 8 + i];
            c1[i] = fmaxf(a, 0.f);
        }
        float o2 = cb2[j];
#pragma unroll
        for (int i = 0; i < 8; i++) o2 += c1[i] * cW2[i * 8 + j];
        cat[DLAT + j] = o2;
    }
    __syncthreads();
    float h = fb1[j];
    for (int k = 0; k < DLAT + 8; k++) h += cat[k] * fW1[k * DLAT + j];
    h1out[(size_t)g * DLAT + j] = leaky(h);
}

__global__ void __launch_bounds__(64) head2(
    const float* __restrict__ h1, const float* __restrict__ fa, const float* __restrict__ fc,
    const float* __restrict__ fW2, const float* __restrict__ fb2,
    float* __restrict__ out) {
    int g = blockIdx.x;
    int j = threadIdx.x;
    __shared__ float hn[DLAT];
    hn[j] = h1[(size_t)g * DLAT + j] * fa[j] + fc[j];
    __syncthreads();
    float o = fb2[j];
    for (int k = 0; k < DLAT; k++) o += hn[k] * fW2[k * DLAT + j];
    out[(size_t)g * DLAT + j] = o;
}

// ================= launch =================
extern "C" void kernel_launch(void* const* d_in, const int* in_sizes, int n_in,
                              void* d_out, int out_size) {
    const float* x      = (const float*)d_in[0];
    const int*   ei     = (const int*)d_in[1];
    const int*   batch  = (const int*)d_in[2];
    const float* feats  = (const float*)d_in[3];
    const float* convW1 = (const float*)d_in[4];
    const float* convb1 = (const float*)d_in[5];
    const float* convg1 = (const float*)d_in[6];
    const float* convbb1= (const float*)d_in[7];
    const float* convW2 = (const float*)d_in[8];
    const float* convb2 = (const float*)d_in[9];
    const float* bng    = (const float*)d_in[10];
    const float* bnb    = (const float*)d_in[11];
    const float* fcW    = (const float*)d_in[12];
    const float* fcb    = (const float*)d_in[13];
    const float* cW1    = (const float*)d_in[14];
    const float* cb1    = (const float*)d_in[15];
    const float* cW2    = (const float*)d_in[16];
    const float* cb2    = (const float*)d_in[17];
    const float* fW1    = (const float*)d_in[18];
    const float* fb1    = (const float*)d_in[19];
    const float* fg     = (const float*)d_in[20];
    const float* fb_    = (const float*)d_in[21];
    const float* fW2    = (const float*)d_in[22];
    const float* fb2    = (const float*)d_in[23];
    float* dout = (float*)d_out;

    int nE = in_sizes[1] / 2;
    const int* src = ei;
    const int* dst = ei + nE;
    int M = in_sizes[0] / DH;
    int G = in_sizes[3] / NCOND;

    uint4 *p_a, *p_h, *p_x, *p_Bpk;
    float *p_bias, *p_sum, *p_sq, *p_a2, *p_c2, *p_pool, *p_pa, *p_pc, *p_h1, *p_fa, *p_fc;
    int *p_cnt, *p_rowptr, *p_bsum, *p_bscan, *p_csr;
    cudaGetSymbolAddress((void**)&p_a, g_a);
    cudaGetSymbolAddress((void**)&p_h, g_h);
    cudaGetSymbolAddress((void**)&p_x, g_x);
    cudaGetSymbolAddress((void**)&p_Bpk, g_Bpk);
    cudaGetSymbolAddress((void**)&p_bias, g_bias);
    cudaGetSymbolAddress((void**)&p_cnt, g_cnt);
    cudaGetSymbolAddress((void**)&p_rowptr, g_rowptr);
    cudaGetSymbolAddress((void**)&p_bsum, g_bsum);
    cudaGetSymbolAddress((void**)&p_bscan, g_bscan);
    cudaGetSymbolAddress((void**)&p_csr, g_csr);
    cudaGetSymbolAddress((void**)&p_sum, g_sum);
    cudaGetSymbolAddress((void**)&p_sq, g_sumsq);
    cudaGetSymbolAddress((void**)&p_a2, g_a2);
    cudaGetSymbolAddress((void**)&p_c2, g_c2);
    cudaGetSymbolAddress((void**)&p_pool, g_pooled);
    cudaGetSymbolAddress((void**)&p_pa, g_pa);
    cudaGetSymbolAddress((void**)&p_pc, g_pc);
    cudaGetSymbolAddress((void**)&p_h1, g_h1);
    cudaGetSymbolAddress((void**)&p_fa, g_fa);
    cudaGetSymbolAddress((void**)&p_fc, g_fc);

    cudaFuncSetAttribute(gemm1_stats, cudaFuncAttributeMaxDynamicSharedMemorySize, GEMM_SMEM);
    cudaFuncSetAttribute(gemm2_pool, cudaFuncAttributeMaxDynamicSharedMemorySize, GEMM_SMEM);

    // ---- CSR build ----
    zerok<<<(N_NODES / 4 + 255) / 256, 256>>>((float4*)p_cnt, N_NODES / 4);
    hist_k<<<(nE + 255) / 256, 256>>>(dst, p_cnt, nE);
    int nb = (M + 1023) / 1024;
    scan_block<<<nb, 1024>>>(p_cnt, p_rowptr, p_bsum, M);
    scan_sums<<<1, 128>>>(p_bsum, p_bscan, nb);
    add_off<<<(M + 255) / 256, 256>>>(p_rowptr, p_bscan, p_cnt, M, nE);
    scatter_k<<<(nE + 255) / 256, 256>>>(src, dst, p_cnt, p_csr, nE);

    // ---- zero stats + pooled in one launch ----
    zero3<<<(N_GRAPHS * DH / 4 + 255) / 256, 256>>>(
        (float4*)p_sum, (float4*)p_sq, (float4*)p_pool, N_GRAPHS * DH / 4);

    int gemmGrid = (M + 255) / 256;
    for (int l = 0; l < 3; l++) {
        gather_i<<<(M + 7) / 8, 256>>>(
            (const float4*)x, (const uint4*)p_x, p_rowptr, p_csr, p_a, M, (l == 0) ? 0 : 1);
        wprep2<<<DH, DH>>>(convW1 + (size_t)l * DH * DH, convb1 + l * DH,
                           nullptr, nullptr, p_Bpk, p_bias, 0);
        gemm1_stats<<<gemmGrid, 256, GEMM_SMEM>>>(
            p_a, p_Bpk, p_bias, (uint32_t*)p_h, p_sum, p_sq, M);
        bn_prep<<<1, DH>>>(p_sum, p_sq, (float)M, convg1 + l * DH, convbb1 + l * DH,
                           p_a2, p_c2, DH);
        wprep2<<<DH, DH>>>(convW2 + (size_t)l * DH * DH, convb2 + l * DH,
                           p_a2, p_c2, p_Bpk, p_bias, 1);
        gemm2_pool<<<gemmGrid, 256, GEMM_SMEM>>>(
            p_h, p_Bpk, p_bias, (uint32_t*)p_x, batch, p_pool, M, (l == 2) ? 1 : 0);
    }

    colstats<<<DH, 256>>>(p_pool, G, DH, bng, bnb, p_pa, p_pc);
    head1<<<G, 64>>>(p_pool, p_pa, p_pc, fcW, fcb, feats, cW1, cb1, cW2, cb2, fW1, fb1, p_h1);
    colstats<<<DLAT, 256>>>(p_h1, G, DLAT, fg, fb_, p_fa, p_fc);
    head2<<<G, 64>>>(p_h1, p_fa, p_fc, fW2, fb2, dout);
}

// round 10
// speedup vs baseline: 1.8648x; 1.0660x over previous
#include <cuda_runtime.h>
#include <cuda_bf16.h>
#include <cstdint>

#define N_NODES 100000
#define N_EDGESC 1600000
#define N_GRAPHS 512
#define DH 128
#define DLAT 64
#define NCOND 7
#define BN_EPS 1e-5f
#define NSM 148

// ================= scratch (device globals) =================
// interleaved rows: 32 uint4 per row; uint4 g = (hi01, lo01, hi23, lo23) for cols 4g..4g+3
__device__ uint4 g_a[N_NODES * 32];     // gather out
__device__ uint4 g_h[N_NODES * 32];     // GEMM1 out
__device__ uint4 g_x[N_NODES * 32];     // GEMM2 out (layer output)
__device__ uint4 g_Bpk[128 * 32];       // fragment-packed weights (bf16 hi/lo)
__device__ float g_bias[DH];
__device__ int g_cnt[N_NODES];
__device__ int g_rowptr[N_NODES + 1];
__device__ int g_bsum[128];
__device__ int g_bscan[128];
__device__ int g_csr[N_EDGESC];
__device__ float g_sum[DH];
__device__ float g_sumsq[DH];
__device__ float g_a2[DH];
__device__ float g_c2[DH];
__device__ float g_pooled[N_GRAPHS * DH];
__device__ float g_pa[DH];
__device__ float g_pc[DH];
__device__ float g_h1[N_GRAPHS * DLAT];
__device__ float g_fa[DLAT];
__device__ float g_fc[DLAT];

// ================= helpers =================
__device__ __forceinline__ float leaky(float x) { return fmaxf(x, 0.2f * x); }
__device__ __forceinline__ void red_add_v2(float* p, float a, float b) {
    asm volatile("red.global.add.v2.f32 [%0], {%1,%2};"
                 :: "l"(p), "f"(a), "f"(b) : "memory");
}
__device__ __forceinline__ uint32_t bf2bits(__nv_bfloat162 v) {
    return *reinterpret_cast<uint32_t*>(&v);
}
__device__ __forceinline__ __nv_bfloat162 bits2bf2(uint32_t v) {
    return *reinterpret_cast<__nv_bfloat162*>(&v);
}
// decode interleaved uint4 (hi01, lo01, hi23, lo23) -> 4 fp32 cols
__device__ __forceinline__ float4 dec4(uint4 v) {
    float2 h0 = __bfloat1622float2(bits2bf2(v.x));
    float2 l0 = __bfloat1622float2(bits2bf2(v.y));
    float2 h1 = __bfloat1622float2(bits2bf2(v.z));
    float2 l1 = __bfloat1622float2(bits2bf2(v.w));
    return make_float4(h0.x + l0.x, h0.y + l0.y, h1.x + l1.x, h1.y + l1.y);
}
// encode 4 fp32 cols -> interleaved uint4 (hi01, lo01, hi23, lo23)
__device__ __forceinline__ uint4 enc4(float4 a) {
    __nv_bfloat162 H0 = __floats2bfloat162_rn(a.x, a.y);
    __nv_bfloat162 H1 = __floats2bfloat162_rn(a.z, a.w);
    float2 f0 = __bfloat1622float2(H0), f1 = __bfloat1622float2(H1);
    __nv_bfloat162 L0 = __floats2bfloat162_rn(a.x - f0.x, a.y - f0.y);
    __nv_bfloat162 L1 = __floats2bfloat162_rn(a.z - f1.x, a.w - f1.y);
    return make_uint4(bf2bits(H0), bf2bits(L0), bf2bits(H1), bf2bits(L1));
}
__device__ __forceinline__ void mma_bf16(float* d, uint32_t a0, uint32_t a1,
                                         uint32_t a2, uint32_t a3,
                                         uint32_t b0, uint32_t b1) {
    asm volatile(
        "mma.sync.aligned.m16n8k16.row.col.f32.bf16.bf16.f32 "
        "{%0,%1,%2,%3}, {%4,%5,%6,%7}, {%8,%9}, {%0,%1,%2,%3};"
        : "+f"(d[0]), "+f"(d[1]), "+f"(d[2]), "+f"(d[3])
        : "r"(a0), "r"(a1), "r"(a2), "r"(a3), "r"(b0), "r"(b1));
}

// ================= zero =================
__global__ void zerok(float4* p, int n4) {
    int i = blockIdx.x * blockDim.x + threadIdx.x;
    if (i < n4) p[i] = make_float4(0.f, 0.f, 0.f, 0.f);
}
__global__ void zero3(float4* sum4, float4* sq4, float4* pool4, int pool4n) {
    int i = blockIdx.x * blockDim.x + threadIdx.x;
    if (i < pool4n) pool4[i] = make_float4(0.f, 0.f, 0.f, 0.f);
    if (i < DH / 4) {
        sum4[i] = make_float4(0.f, 0.f, 0.f, 0.f);
        sq4[i] = make_float4(0.f, 0.f, 0.f, 0.f);
    }
}

// ================= CSR build =================
__global__ void hist_k(const int* __restrict__ dst, int* __restrict__ cnt, int nE) {
    int i = blockIdx.x * blockDim.x + threadIdx.x;
    if (i < nE) atomicAdd(&cnt[dst[i]], 1);
}
__global__ void scan_block(const int* __restrict__ cnt, int* __restrict__ excl,
                           int* __restrict__ bsum, int n) {
    __shared__ int sm[1024];
    int i = blockIdx.x * 1024 + threadIdx.x;
    int v = (i < n) ? cnt[i] : 0;
    sm[threadIdx.x] = v;
    __syncthreads();
    for (int off = 1; off < 1024; off <<= 1) {
        int t = (threadIdx.x >= off) ? sm[threadIdx.x - off] : 0;
        __syncthreads();
        sm[threadIdx.x] += t;
        __syncthreads();
    }
    if (i < n) excl[i] = sm[threadIdx.x] - v;
    if (threadIdx.x == 1023) bsum[blockIdx.x] = sm[1023];
}
__global__ void scan_sums(const int* __restrict__ bsum, int* __restrict__ bscan, int nb) {
    __shared__ int sm[128];
    int t = threadIdx.x;
    int v = (t < nb) ? bsum[t] : 0;
    sm[t] = v;
    __syncthreads();
    for (int off = 1; off < 128; off <<= 1) {
        int u = (t >= off) ? sm[t - off] : 0;
        __syncthreads();
        sm[t] += u;
        __syncthreads();
    }
    if (t < nb) bscan[t] = sm[t] - v;
}
__global__ void add_off(int* __restrict__ rowptr, const int* __restrict__ bscan,
                        int* __restrict__ cursor, int n, int nE) {
    int i = blockIdx.x * blockDim.x + threadIdx.x;
    if (i < n) {
        int v = rowptr[i] + bscan[i >> 10];
        rowptr[i] = v;
        cursor[i] = v;
    }
    if (i == 0) rowptr[n] = nE;
}
__global__ void scatter_k(const int* __restrict__ src, const int* __restrict__ dst,
                          int* __restrict__ cursor, int* __restrict__ csr, int nE) {
    int i = blockIdx.x * blockDim.x + threadIdx.x;
    if (i < nE) {
        int pos = atomicAdd(&cursor[dst[i]], 1);
        csr[pos] = src[i];
    }
}

// ================= gather: h = x[node] + sum_nb x[nb]; interleaved in/out =================
__global__ void __launch_bounds__(256) gather_i(
    const float4* __restrict__ xf, const uint4* __restrict__ xc,
    const int* __restrict__ rowptr, const int* __restrict__ csr,
    uint4* __restrict__ out, int M, int splitIn) {
    int node = blockIdx.x * 8 + (threadIdx.x >> 5);
    if (node >= M) return;
    int lane = threadIdx.x & 31;
    int e0 = __ldg(rowptr + node), e1 = __ldg(rowptr + node + 1);
    float4 acc;
    if (!splitIn) {
        acc = __ldg(xf + (size_t)node * 32 + lane);
        int e = e0;
        for (; e + 8 <= e1; e += 8) {
            int s[8];
#pragma unroll
            for (int u = 0; u < 8; u++) s[u] = __ldg(csr + e + u);
            float4 v[8];
#pragma unroll
            for (int u = 0; u < 8; u++) v[u] = __ldg(xf + (size_t)s[u] * 32 + lane);
#pragma unroll
            for (int u = 0; u < 8; u++) {
                acc.x += v[u].x; acc.y += v[u].y; acc.z += v[u].z; acc.w += v[u].w;
            }
        }
        for (; e < e1; e++) {
            int s = __ldg(csr + e);
            float4 v = __ldg(xf + (size_t)s * 32 + lane);
            acc.x += v.x; acc.y += v.y; acc.z += v.z; acc.w += v.w;
        }
    } else {
        acc = dec4(__ldg(xc + (size_t)node * 32 + lane));
        int e = e0;
        for (; e + 8 <= e1; e += 8) {
            int s[8];
#pragma unroll
            for (int u = 0; u < 8; u++) s[u] = __ldg(csr + e + u);
            uint4 w[8];
#pragma unroll
            for (int u = 0; u < 8; u++) w[u] = __ldg(xc + (size_t)s[u] * 32 + lane);
#pragma unroll
            for (int u = 0; u < 8; u++) {
                float4 v = dec4(w[u]);
                acc.x += v.x; acc.y += v.y; acc.z += v.z; acc.w += v.w;
            }
        }
        for (; e < e1; e++) {
            int s = __ldg(csr + e);
            float4 v = dec4(__ldg(xc + (size_t)s * 32 + lane));
            acc.x += v.x; acc.y += v.y; acc.z += v.z; acc.w += v.w;
        }
    }
    out[(size_t)node * 32 + lane] = enc4(acc);
}

// ================= weight prep: bf16 hi/lo fragment packing + folded bias =================
__global__ void __launch_bounds__(128) wprep2(
    const float* __restrict__ W, const float* __restrict__ bvec,
    const float* __restrict__ a, const float* __restrict__ c,
    uint4* __restrict__ Bpk, float* __restrict__ bout, int hasAff) {
    int n = blockIdx.x, k = threadIdx.x;
    float w = W[k * DH + n];
    float ws = hasAff ? a[k] * w : w;
    __nv_bfloat16 hi = __float2bfloat16(ws);
    __nv_bfloat16 lo = __float2bfloat16(ws - __bfloat162float(hi));
    int ks = k >> 4, kr = k & 15;
    int slot = kr >> 3;
    int qid = (kr & 7) >> 1;
    int half = kr & 1;
    int t = n >> 3, gid = n & 7;
    int lane = gid * 4 + qid;
    __nv_bfloat16* p = reinterpret_cast<__nv_bfloat16*>(Bpk) +
                       ((size_t)(ks * 16 + t) * 32 + lane) * 8;
    p[slot * 2 + half] = hi;
    p[4 + slot * 2 + half] = lo;
    __shared__ float red[DH];
    red[k] = hasAff ? c[k] * w : 0.f;
    __syncthreads();
    for (int off = 64; off > 0; off >>= 1) {
        if (k < off) red[k] += red[k + off];
        __syncthreads();
    }
    if (k == 0) bout[n] = bvec[n] + red[0];
}

// ================= smem layout for GEMMs (256-row tiles, persistent) =================
#define ASW 68                             // uint32 words per A-plane row (padded)
#define A_ROWS 256
#define SM_AL_OFF (A_ROWS * ASW * 4)       // 69632
#define SM_B_OFF (2 * A_ROWS * ASW * 4)    // 139264
#define SM_BIAS_OFF (SM_B_OFF + 65536)     // 204800
#define SM_SACC_OFF (SM_BIAS_OFF + 512)    // 205312
#define GEMM_SMEM (SM_SACC_OFF + 1024)     // 206336

// ================= per-tile A staging + mainloop (3xBF16, 2 m-tiles/warp) =================
__device__ __forceinline__ void stage_A(const uint4* __restrict__ A, uint32_t* Ash,
                                        uint32_t* Asl, int tid, int row0, int M) {
#pragma unroll
    for (int it = 0; it < 32; it++) {
        int idx = it * 256 + tid;
        int r = idx >> 5, g = idx & 31;
        int gr = row0 + r;
        uint4 v = make_uint4(0u, 0u, 0u, 0u);
        if (gr < M) v = __ldg(A + (size_t)gr * 32 + g);
        *(uint2*)(Ash + r * ASW + 2 * g) = make_uint2(v.x, v.z);  // hi01, hi23
        *(uint2*)(Asl + r * ASW + 2 * g) = make_uint2(v.y, v.w);  // lo01, lo23
    }
}

__device__ __forceinline__ void mainloop(
    const uint32_t* Ash, const uint32_t* Asl, const uint4* Bs,
    int warp, int lane, float acc[2][16][4]) {
    int m0 = warp * 32;
    int gid = lane >> 2, qid = lane & 3;
#pragma unroll
    for (int mt = 0; mt < 2; mt++)
#pragma unroll
        for (int t = 0; t < 16; t++)
#pragma unroll
            for (int j = 0; j < 4; j++) acc[mt][t][j] = 0.f;

    const uint32_t *rh0[2], *rh1[2], *rl0[2], *rl1[2];
#pragma unroll
    for (int mt = 0; mt < 2; mt++) {
        rh0[mt] = Ash + (m0 + 16 * mt + gid) * ASW;
        rh1[mt] = Ash + (m0 + 16 * mt + gid + 8) * ASW;
        rl0[mt] = Asl + (m0 + 16 * mt + gid) * ASW;
        rl1[mt] = Asl + (m0 + 16 * mt + gid + 8) * ASW;
    }
#pragma unroll
    for (int ks = 0; ks < 8; ks++) {
        int kb = ks * 8 + qid;
        uint32_t Ahf[2][4], Alf[2][4];
#pragma unroll
        for (int mt = 0; mt < 2; mt++) {
            Ahf[mt][0] = rh0[mt][kb]; Ahf[mt][1] = rh1[mt][kb];
            Ahf[mt][2] = rh0[mt][kb + 4]; Ahf[mt][3] = rh1[mt][kb + 4];
            Alf[mt][0] = rl0[mt][kb]; Alf[mt][1] = rl1[mt][kb];
            Alf[mt][2] = rl0[mt][kb + 4]; Alf[mt][3] = rl1[mt][kb + 4];
        }
        const uint4* bp = Bs + ks * 512 + lane;
#pragma unroll
        for (int t = 0; t < 16; t++) {
            uint4 bv = bp[t * 32];
#pragma unroll
            for (int mt = 0; mt < 2; mt++) {
                mma_bf16(acc[mt][t], Ahf[mt][0], Ahf[mt][1], Ahf[mt][2], Ahf[mt][3], bv.x, bv.y);
                mma_bf16(acc[mt][t], Ahf[mt][0], Ahf[mt][1], Ahf[mt][2], Ahf[mt][3], bv.z, bv.w);
                mma_bf16(acc[mt][t], Alf[mt][0], Alf[mt][1], Alf[mt][2], Alf[mt][3], bv.x, bv.y);
            }
        }
    }
}

// epilogue pack: 2 cols -> adjacent (hi, lo) uint2 store at word 2*j
__device__ __forceinline__ void store_pair(uint32_t* orow, int j, float v0, float v1) {
    __nv_bfloat162 H = __floats2bfloat162_rn(v0, v1);
    float2 f = __bfloat1622float2(H);
    __nv_bfloat162 L = __floats2bfloat162_rn(v0 - f.x, v1 - f.y);
    *(uint2*)(orow + 2 * j) = make_uint2(bf2bits(H), bf2bits(L));
}

// ================= GEMM1 persistent: + leaky + interleaved out + fused column stats =================
__global__ void __launch_bounds__(256, 1) gemm1_stats(
    const uint4* __restrict__ A, const uint4* __restrict__ Bpk,
    const float* __restrict__ bias, uint32_t* __restrict__ out,
    float* __restrict__ gsum, float* __restrict__ gsq, int M, int nTiles) {
    extern __shared__ char smem[];
    uint32_t* Ash = (uint32_t*)smem;
    uint32_t* Asl = (uint32_t*)(smem + SM_AL_OFF);
    uint4* Bs = (uint4*)(smem + SM_B_OFF);
    float* sb = (float*)(smem + SM_BIAS_OFF);
    float* sAcc = (float*)(smem + SM_SACC_OFF);
    int tid = threadIdx.x;
    int warp = tid >> 5, lane = tid & 31;
    int gid = lane >> 2, qid = lane & 3;

    if (tid < 128) sb[tid] = bias[tid];
    sAcc[tid] = 0.f;
#pragma unroll
    for (int it = 0; it < 16; it++) Bs[it * 256 + tid] = __ldg(Bpk + it * 256 + tid);

    for (int tile = blockIdx.x; tile < nTiles; tile += NSM) {
        int row0 = tile << 8;
        __syncthreads();   // prior-tile scratch reads done; B/bias visible on first iter
        stage_A(A, Ash, Asl, tid, row0, M);
        __syncthreads();
        float acc[2][16][4];
        mainloop(Ash, Asl, Bs, warp, lane, acc);

        float cs[32], cq[32];
#pragma unroll
        for (int i = 0; i < 32; i++) { cs[i] = 0.f; cq[i] = 0.f; }
#pragma unroll
        for (int mt = 0; mt < 2; mt++) {
            int r0 = row0 + warp * 32 + 16 * mt + gid;
            int r1 = r0 + 8;
            uint32_t* orow0 = out + (size_t)r0 * 128;
            uint32_t* orow1 = out + (size_t)r1 * 128;
#pragma unroll
            for (int t = 0; t < 16; t++) {
                int c = t * 8 + qid * 2;
                int j = t * 4 + qid;
                float b0 = sb[c], b1 = sb[c + 1];
                float v00 = 0.f, v01 = 0.f, v10 = 0.f, v11 = 0.f;
                if (r0 < M) {
                    v00 = leaky(acc[mt][t][0] + b0);
                    v01 = leaky(acc[mt][t][1] + b1);
                    store_pair(orow0, j, v00, v01);
                }
                if (r1 < M) {
                    v10 = leaky(acc[mt][t][2] + b0);
                    v11 = leaky(acc[mt][t][3] + b1);
                    store_pair(orow1, j, v10, v11);
                }
                cs[2 * t] += v00 + v10;
                cs[2 * t + 1] += v01 + v11;
                cq[2 * t] += v00 * v00 + v10 * v10;
                cq[2 * t + 1] += v01 * v01 + v11 * v11;
            }
        }

        __syncthreads();   // all mainloop smem reads done before scratch overwrite
        float* ssum = (float*)smem;          // [64][128] over A region
        float* ssq = (float*)smem + 8192;
        int slot = warp * 8 + gid;
#pragma unroll
        for (int t = 0; t < 16; t++) {
            int c = t * 8 + qid * 2;
            ssum[slot * 128 + c] = cs[2 * t];
            ssum[slot * 128 + c + 1] = cs[2 * t + 1];
            ssq[slot * 128 + c] = cq[2 * t];
            ssq[slot * 128 + c + 1] = cq[2 * t + 1];
        }
        __syncthreads();
        if (tid < 128) {
            float s = 0.f;
#pragma unroll
            for (int w = 0; w < 64; w++) s += ssum[w * 128 + tid];
            sAcc[tid] += s;
        } else {
            int c = tid - 128;
            float q = 0.f;
#pragma unroll
            for (int w = 0; w < 64; w++) q += ssq[w * 128 + c];
            sAcc[tid] += q;
        }
    }
    __syncthreads();
    if (tid < 128) atomicAdd(&gsum[tid], sAcc[tid]);
    else atomicAdd(&gsq[tid - 128], sAcc[tid]);
}

// ================= GEMM2 persistent: + leaky; mode0: store; mode1: pool-only =================
__global__ void __launch_bounds__(256, 1) gemm2_pool(
    const uint4* __restrict__ A, const uint4* __restrict__ Bpk,
    const float* __restrict__ bias, uint32_t* __restrict__ out,
    const int* __restrict__ batch, float* __restrict__ pooled,
    int M, int nTiles, int doPool) {
    extern __shared__ char smem[];
    uint32_t* Ash = (uint32_t*)smem;
    uint32_t* Asl = (uint32_t*)(smem + SM_AL_OFF);
    uint4* Bs = (uint4*)(smem + SM_B_OFF);
    float* sb = (float*)(smem + SM_BIAS_OFF);
    int tid = threadIdx.x;
    int warp = tid >> 5, lane = tid & 31;
    int gid = lane >> 2, qid = lane & 3;

    if (tid < 128) sb[tid] = bias[tid];
#pragma unroll
    for (int it = 0; it < 16; it++) Bs[it * 256 + tid] = __ldg(Bpk + it * 256 + tid);

    for (int tile = blockIdx.x; tile < nTiles; tile += NSM) {
        int row0 = tile << 8;
        __syncthreads();
        stage_A(A, Ash, Asl, tid, row0, M);
        __syncthreads();
        float acc[2][16][4];
        mainloop(Ash, Asl, Bs, warp, lane, acc);

        if (!doPool) {
#pragma unroll
            for (int mt = 0; mt < 2; mt++) {
                int r0 = row0 + warp * 32 + 16 * mt + gid;
                int r1 = r0 + 8;
                uint32_t* orow0 = out + (size_t)r0 * 128;
                uint32_t* orow1 = out + (size_t)r1 * 128;
#pragma unroll
                for (int t = 0; t < 16; t++) {
                    int c = t * 8 + qid * 2;
                    int j = t * 4 + qid;
                    float b0 = sb[c], b1 = sb[c + 1];
                    if (r0 < M)
                        store_pair(orow0, j, leaky(acc[mt][t][0] + b0), leaky(acc[mt][t][1] + b1));
                    if (r1 < M)
                        store_pair(orow1, j, leaky(acc[mt][t][2] + b0), leaky(acc[mt][t][3] + b1));
                }
            }
        } else {
#pragma unroll
            for (int mt = 0; mt < 2; mt++) {
                int r0 = row0 + warp * 32 + 16 * mt + gid;
                int r1 = r0 + 8;
                int b0g = (r0 < M) ? __ldg(batch + r0) : 0;
                int b1g = (r1 < M) ? __ldg(batch + r1) : 0;
#pragma unroll
                for (int t = 0; t < 16; t++) {
                    int c = t * 8 + qid * 2;
                    float b0 = sb[c], b1 = sb[c + 1];
                    if (r0 < M)
                        red_add_v2(pooled + (size_t)b0g * DH + c,
                                   leaky(acc[mt][t][0] + b0), leaky(acc[mt][t][1] + b1));
                    if (r1 < M)
                        red_add_v2(pooled + (size_t)b1g * DH + c,
                                   leaky(acc[mt][t][2] + b0), leaky(acc[mt][t][3] + b1));
                }
            }
        }
    }
}

// ================= sums -> folded BN affine (also zeroes accumulators) =================
__global__ void bn_prep(float* __restrict__ sum, float* __restrict__ sumsq,
                        float n, const float* __restrict__ g, const float* __restrict__ b,
                        float* __restrict__ oa, float* __restrict__ oc, int D) {
    int c = threadIdx.x;
    if (c < D) {
        float m = sum[c] / n;
        float v = sumsq[c] / n - m * m;
        float r = rsqrtf(v + BN_EPS);
        oa[c] = g[c] * r;
        oc[c] = b[c] - g[c] * m * r;
        sum[c] = 0.f;
        sumsq[c] = 0.f;
    }
}

// ================= small column stats (pooled / h1) =================
__global__ void colstats(const float* __restrict__ data, int rows, int cols,
                         const float* __restrict__ g, const float* __restrict__ b,
                         float* __restrict__ oa, float* __restrict__ oc) {
    int col = blockIdx.x;
    int t = threadIdx.x;
    float s = 0.f, q = 0.f;
    for (int r = t; r < rows; r += blockDim.x) {
        float v = data[(size_t)r * cols + col];
        s += v; q += v * v;
    }
    __shared__ float ss[256], qq[256];
    ss[t] = s; qq[t] = q;
    __syncthreads();
    for (int off = 128; off > 0; off >>= 1) {
        if (t < off) { ss[t] += ss[t + off]; qq[t] += qq[t + off]; }
        __syncthreads();
    }
    if (t == 0) {
        float m = ss[0] / rows;
        float v = qq[0] / rows - m * m;
        float r = rsqrtf(v + BN_EPS);
        oa[col] = g[col] * r;
        oc[col] = b[col] - g[col] * m * r;
    }
}

// ================= head =================
__global__ void __launch_bounds__(64) head1(
    const float* __restrict__ pooled, const float* __restrict__ pa, const float* __restrict__ pc,
    const float* __restrict__ fcW, const float* __restrict__ fcb,
    const float* __restrict__ feats,
    const float* __restrict__ cW1, const float* __restrict__ cb1,
    const float* __restrict__ cW2, const float* __restrict__ cb2,
    const float* __restrict__ fW1, const float* __restrict__ fb1,
    float* __restrict__ h1out) {
    int g = blockIdx.x;
    int j = threadIdx.x;
    __shared__ float cat[DLAT + 8];
    float o = fcb[j];
    const float* pr = pooled + (size_t)g * DH;
    for (int k = 0; k < DH; k++) o += (pr[k] * pa[k] + pc[k]) * fcW[k * DLAT + j];
    cat[j] = o;
    if (j < 8) {
        float c1[8];
#pragma unroll
        for (int i = 0; i < 8; i++) {
            float a = cb1[i];
#pragma unroll
            for (int m = 0; m < NCOND; m++) a += feats[g * NCOND + m] * cW1[m * 8 + i];
            c1[i] = fmaxf(a, 0.f);
        }
        float o2 = cb2[j];
#pragma unroll
        for (int i = 0; i < 8; i++) o2 += c1[i] * cW2[i * 8 + j];
        cat[DLAT + j] = o2;
    }
    __syncthreads();
    float h = fb1[j];
    for (int k = 0; k < DLAT + 8; k++) h += cat[k] * fW1[k * DLAT + j];
    h1out[(size_t)g * DLAT + j] = leaky(h);
}

__global__ void __launch_bounds__(64) head2(
    const float* __restrict__ h1, const float* __restrict__ fa, const float* __restrict__ fc,
    const float* __restrict__ fW2, const float* __restrict__ fb2,
    float* __restrict__ out) {
    int g = blockIdx.x;
    int j = threadIdx.x;
    __shared__ float hn[DLAT];
    hn[j] = h1[(size_t)g * DLAT + j] * fa[j] + fc[j];
    __syncthreads();
    float o = fb2[j];
    for (int k = 0; k < DLAT; k++) o += hn[k] * fW2[k * DLAT + j];
    out[(size_t)g * DLAT + j] = o;
}

// ================= launch =================
extern "C" void kernel_launch(void* const* d_in, const int* in_sizes, int n_in,
                              void* d_out, int out_size) {
    const float* x      = (const float*)d_in[0];
    const int*   ei     = (const int*)d_in[1];
    const int*   batch  = (const int*)d_in[2];
    const float* feats  = (const float*)d_in[3];
    const float* convW1 = (const float*)d_in[4];
    const float* convb1 = (const float*)d_in[5];
    const float* convg1 = (const float*)d_in[6];
    const float* convbb1= (const float*)d_in[7];
    const float* convW2 = (const float*)d_in[8];
    const float* convb2 = (const float*)d_in[9];
    const float* bng    = (const float*)d_in[10];
    const float* bnb    = (const float*)d_in[11];
    const float* fcW    = (const float*)d_in[12];
    const float* fcb    = (const float*)d_in[13];
    const float* cW1    = (const float*)d_in[14];
    const float* cb1    = (const float*)d_in[15];
    const float* cW2    = (const float*)d_in[16];
    const float* cb2    = (const float*)d_in[17];
    const float* fW1    = (const float*)d_in[18];
    const float* fb1    = (const float*)d_in[19];
    const float* fg     = (const float*)d_in[20];
    const float* fb_    = (const float*)d_in[21];
    const float* fW2    = (const float*)d_in[22];
    const float* fb2    = (const float*)d_in[23];
    float* dout = (float*)d_out;

    int nE = in_sizes[1] / 2;
    const int* src = ei;
    const int* dst = ei + nE;
    int M = in_sizes[0] / DH;
    int G = in_sizes[3] / NCOND;

    uint4 *p_a, *p_h, *p_x, *p_Bpk;
    float *p_bias, *p_sum, *p_sq, *p_a2, *p_c2, *p_pool, *p_pa, *p_pc, *p_h1, *p_fa, *p_fc;
    int *p_cnt, *p_rowptr, *p_bsum, *p_bscan, *p_csr;
    cudaGetSymbolAddress((void**)&p_a, g_a);
    cudaGetSymbolAddress((void**)&p_h, g_h);
    cudaGetSymbolAddress((void**)&p_x, g_x);
    cudaGetSymbolAddress((void**)&p_Bpk, g_Bpk);
    cudaGetSymbolAddress((void**)&p_bias, g_bias);
    cudaGetSymbolAddress((void**)&p_cnt, g_cnt);
    cudaGetSymbolAddress((void**)&p_rowptr, g_rowptr);
    cudaGetSymbolAddress((void**)&p_bsum, g_bsum);
    cudaGetSymbolAddress((void**)&p_bscan, g_bscan);
    cudaGetSymbolAddress((void**)&p_csr, g_csr);
    cudaGetSymbolAddress((void**)&p_sum, g_sum);
    cudaGetSymbolAddress((void**)&p_sq, g_sumsq);
    cudaGetSymbolAddress((void**)&p_a2, g_a2);
    cudaGetSymbolAddress((void**)&p_c2, g_c2);
    cudaGetSymbolAddress((void**)&p_pool, g_pooled);
    cudaGetSymbolAddress((void**)&p_pa, g_pa);
    cudaGetSymbolAddress((void**)&p_pc, g_pc);
    cudaGetSymbolAddress((void**)&p_h1, g_h1);
    cudaGetSymbolAddress((void**)&p_fa, g_fa);
    cudaGetSymbolAddress((void**)&p_fc, g_fc);

    cudaFuncSetAttribute(gemm1_stats, cudaFuncAttributeMaxDynamicSharedMemorySize, GEMM_SMEM);
    cudaFuncSetAttribute(gemm2_pool, cudaFuncAttributeMaxDynamicSharedMemorySize, GEMM_SMEM);

    // ---- CSR build ----
    zerok<<<(N_NODES / 4 + 255) / 256, 256>>>((float4*)p_cnt, N_NODES / 4);
    hist_k<<<(nE + 255) / 256, 256>>>(dst, p_cnt, nE);
    int nb = (M + 1023) / 1024;
    scan_block<<<nb, 1024>>>(p_cnt, p_rowptr, p_bsum, M);
    scan_sums<<<1, 128>>>(p_bsum, p_bscan, nb);
    add_off<<<(M + 255) / 256, 256>>>(p_rowptr, p_bscan, p_cnt, M, nE);
    scatter_k<<<(nE + 255) / 256, 256>>>(src, dst, p_cnt, p_csr, nE);

    // ---- zero stats + pooled in one launch ----
    zero3<<<(N_GRAPHS * DH / 4 + 255) / 256, 256>>>(
        (float4*)p_sum, (float4*)p_sq, (float4*)p_pool, N_GRAPHS * DH / 4);

    int nTiles = (M + 255) / 256;
    for (int l = 0; l < 3; l++) {
        gather_i<<<(M + 7) / 8, 256>>>(
            (const float4*)x, (const uint4*)p_x, p_rowptr, p_csr, p_a, M, (l == 0) ? 0 : 1);
        wprep2<<<DH, DH>>>(convW1 + (size_t)l * DH * DH, convb1 + l * DH,
                           nullptr, nullptr, p_Bpk, p_bias, 0);
        gemm1_stats<<<NSM, 256, GEMM_SMEM>>>(
            p_a, p_Bpk, p_bias, (uint32_t*)p_h, p_sum, p_sq, M, nTiles);
        bn_prep<<<1, DH>>>(p_sum, p_sq, (float)M, convg1 + l * DH, convbb1 + l * DH,
                           p_a2, p_c2, DH);
        wprep2<<<DH, DH>>>(convW2 + (size_t)l * DH * DH, convb2 + l * DH,
                           p_a2, p_c2, p_Bpk, p_bias, 1);
        gemm2_pool<<<NSM, 256, GEMM_SMEM>>>(
            p_h, p_Bpk, p_bias, (uint32_t*)p_x, batch, p_pool, M, nTiles, (l == 2) ? 1 : 0);
    }

    colstats<<<DH, 256>>>(p_pool, G, DH, bng, bnb, p_pa, p_pc);
    head1<<<G, 64>>>(p_pool, p_pa, p_pc, fcW, fcb, feats, cW1, cb1, cW2, cb2, fW1, fb1, p_h1);
    colstats<<<DLAT, 256>>>(p_h1, G, DLAT, fg, fb_, p_fa, p_fc);
    head2<<<G, 64>>>(p_h1, p_fa, p_fc, fW2, fb2, dout);
}